// round 5
// baseline (speedup 1.0000x reference)
#include <cuda_runtime.h>
#include <math.h>

#define Tt 128
#define Bb 32
#define PH 256
#define WH 1024
#define PV 45
#define WV 32000
#define PE 64
#define WE 512

// ---------------- device scratch (no allocations) ----------------
__device__ float g_Apos[Tt*Bb*4*PH];        // [4096][1024] input proj + biases (pos cell)
__device__ float g_Aw0 [Tt*Bb*4*WH];        // [4096][4096] input proj + biases (word cell0)
__device__ float g_ph  [(Tt+1)*Bb*PH];      // pos hidden slots
__device__ float g_wh0 [(Tt+1)*Bb*WH];      // word l0 hidden slots
__device__ float g_wh1 [(Tt+1)*Bb*WH];      // word l1 hidden slots (= w_outs)
__device__ float g_pc  [Bb*PH];
__device__ float g_wc0 [Bb*WH];
__device__ float g_wc1 [Bb*WH];
__device__ float g_wmid[Tt*Bb*WE];          // [4096][512]

// ---------------- packed f32x2 helpers ----------------
__device__ __forceinline__ unsigned long long fma2(unsigned long long a,
                                                   unsigned long long b,
                                                   unsigned long long c) {
    unsigned long long d;
    asm("fma.rn.f32x2 %0, %1, %2, %3;" : "=l"(d) : "l"(a), "l"(b), "l"(c));
    return d;
}
__device__ __forceinline__ float acc_sum(unsigned long long v) {
    float x, y;
    asm("mov.b64 {%0,%1}, %2;" : "=f"(x), "=f"(y) : "l"(v));
    return x + y;
}
__device__ __forceinline__ float sigf(float x) { return 1.0f / (1.0f + expf(-x)); }

// ---------------- init ----------------
__global__ void zero_init() {
    int i = blockIdx.x * blockDim.x + threadIdx.x;
    if (i < Bb*PH) { g_ph[i] = 0.f; g_pc[i] = 0.f; }
    if (i < Bb*WH) { g_wh0[i] = 0.f; g_wh1[i] = 0.f; g_wc0[i] = 0.f; g_wc1[i] = 0.f; }
}

// ---------------- generic NT GEMM ----------------
// C[m,n] = A(row gather[m] or m)[0..K) . Bm[n][0..K) + bias1[n] + bias2[n]
// 64x64 tile, BK=32, 256 threads, 4m x 4n per thread, k-packed f32x2.
__global__ __launch_bounds__(256) void gemm_nt(
    const float* __restrict__ A, const int* __restrict__ gather, int lda,
    const float* __restrict__ Bm, int ldb,
    float* __restrict__ C, int ldc, int K,
    const float* __restrict__ bias1, const float* __restrict__ bias2)
{
    __shared__ __align__(16) float As[64][36];
    __shared__ __align__(16) float Bs[64][36];
    const int tid = threadIdx.x;
    const int m0 = blockIdx.y * 64, n0 = blockIdx.x * 64;
    const int tn = tid & 15, tm = tid >> 4;

    unsigned long long acc[4][4];
#pragma unroll
    for (int r = 0; r < 4; r++)
#pragma unroll
        for (int s = 0; s < 4; s++) acc[r][s] = 0ull;

    for (int k0 = 0; k0 < K; k0 += 32) {
#pragma unroll
        for (int i = 0; i < 2; i++) {
            int idx = tid + i * 256;
            int row = idx >> 3, ks = idx & 7;
            int gr = gather ? gather[m0 + row] : (m0 + row);
            *(float4*)&As[row][ks*4] = *(const float4*)(A  + (size_t)gr * lda + k0 + ks*4);
            *(float4*)&Bs[row][ks*4] = *(const float4*)(Bm + (size_t)(n0 + row) * ldb + k0 + ks*4);
        }
        __syncthreads();
#pragma unroll
        for (int kk = 0; kk < 32; kk += 4) {
            ulonglong2 av[4], bv[4];
#pragma unroll
            for (int r = 0; r < 4; r++) av[r] = *(const ulonglong2*)&As[tm*4 + r][kk];
#pragma unroll
            for (int s = 0; s < 4; s++) bv[s] = *(const ulonglong2*)&Bs[tn + 16*s][kk];
#pragma unroll
            for (int r = 0; r < 4; r++)
#pragma unroll
                for (int s = 0; s < 4; s++) {
                    acc[r][s] = fma2(av[r].x, bv[s].x, acc[r][s]);
                    acc[r][s] = fma2(av[r].y, bv[s].y, acc[r][s]);
                }
        }
        __syncthreads();
    }
#pragma unroll
    for (int s = 0; s < 4; s++) {
        int n = n0 + tn + 16*s;
        float badd = 0.f;
        if (bias1) badd += bias1[n];
        if (bias2) badd += bias2[n];
#pragma unroll
        for (int r = 0; r < 4; r++) {
            int m = m0 + tm*4 + r;
            C[(size_t)m * ldc + n] = acc_sum(acc[r][s]) + badd;
        }
    }
}

// ---------------- fused LSTM cell ----------------
// gates[b][j] = base(b,j) + x0[b]·W0[j] + x1[b]·W1[j]; j = gate*H + h
// base = pre[b][j] (if pre) else bih[j]+bhh[j]. Then pointwise LSTM update.
// Block covers HPB h-cols x 4 gates x 32 batch rows. Threads = 32*HPB.
template <int HPB>
__global__ void lstm_cell(
    const float* __restrict__ pre,
    const float* __restrict__ bih, const float* __restrict__ bhh,
    const float* __restrict__ x0, int ldx0, const float* __restrict__ W0, int ldW0, int K0,
    const float* __restrict__ x1, int ldx1, const float* __restrict__ W1, int ldW1, int K1,
    float* __restrict__ c_st, float* __restrict__ h_out, int H)
{
    constexpr int GRP = 4 * HPB;
    constexpr int NT  = 32 * HPB;
    __shared__ __align__(16) float xs[32][36];
    __shared__ __align__(16) float ws[GRP][36];
    const int tid  = threadIdx.x;
    const int c    = tid % GRP;       // col within block (gate-major)
    const int rg   = tid / GRP;       // 0..7 -> 4 batch rows each
    const int gate = c / HPB;
    const int hh   = c % HPB;
    const int h    = blockIdx.x * HPB + hh;
    const int j    = gate * H + h;

    unsigned long long acc[4] = {0ull, 0ull, 0ull, 0ull};

    const float* xp = x0; const float* Wp = W0;
    int ldx = ldx0, ldW = ldW0, K = K0;
#pragma unroll 1
    for (int part = 0; part < 2; part++) {
        if (part) { xp = x1; Wp = W1; ldx = ldx1; ldW = ldW1; K = K1; }
        for (int k0 = 0; k0 < K; k0 += 32) {
            for (int idx = tid; idx < 256; idx += NT) {
                int row = idx >> 3, ks = idx & 7;
                *(float4*)&xs[row][ks*4] = *(const float4*)(xp + (size_t)row * ldx + k0 + ks*4);
            }
            {
                int wr = tid >> 3, ks = tid & 7;   // NT/8 == GRP rows, one float4 each
                int jr = (wr / HPB) * H + blockIdx.x * HPB + (wr % HPB);
                *(float4*)&ws[wr][ks*4] = *(const float4*)(Wp + (size_t)jr * ldW + k0 + ks*4);
            }
            __syncthreads();
#pragma unroll
            for (int kk = 0; kk < 32; kk += 4) {
                ulonglong2 wv = *(const ulonglong2*)&ws[c][kk];
#pragma unroll
                for (int r = 0; r < 4; r++) {
                    ulonglong2 xv = *(const ulonglong2*)&xs[rg*4 + r][kk];
                    acc[r] = fma2(xv.x, wv.x, acc[r]);
                    acc[r] = fma2(xv.y, wv.y, acc[r]);
                }
            }
            __syncthreads();
        }
    }

    const int lane = tid & 31;
    const int base = (lane % HPB) + (lane / GRP) * GRP;  // lane of gate0, same h/rows
#pragma unroll
    for (int r = 0; r < 4; r++) {
        int b = rg*4 + r;
        float v = acc_sum(acc[r]);
        float badd;
        if (pre) badd = pre[(size_t)b * (4*H) + j];
        else     badd = bih[j] + bhh[j];
        v += badd;
        float iv = __shfl_sync(0xffffffffu, v, base);
        float fv = __shfl_sync(0xffffffffu, v, base + HPB);
        float gv = __shfl_sync(0xffffffffu, v, base + 2*HPB);
        float ov = __shfl_sync(0xffffffffu, v, base + 3*HPB);
        if (gate == 0) {
            float cp = c_st[b*H + h];
            float cn = sigf(fv) * cp + sigf(iv) * tanhf(gv);
            c_st[b*H + h]  = cn;
            h_out[b*H + h] = sigf(ov) * tanhf(cn);
        }
    }
}

// ---------------- pos head: Linear(256->45) + log-softmax, one block per row ----------------
__global__ void pos_head(const float* __restrict__ pouts,
                         const float* __restrict__ W, const float* __restrict__ bias,
                         float* __restrict__ out)
{
    __shared__ float sv[64];
    __shared__ float sred[2];
    int r = blockIdx.x, jt = threadIdx.x;
    const float* x = pouts + (size_t)r * PH;
    float v = 0.f;
    if (jt < PV) {
        float s = bias[jt];
        const float* w = W + (size_t)jt * PH;
#pragma unroll 4
        for (int k = 0; k < PH; k++) s += x[k] * w[k];
        v = s;
    }
    sv[jt] = v;
    __syncthreads();
    if (jt == 0) {
        float m = sv[0];
        for (int i = 1; i < PV; i++) m = fmaxf(m, sv[i]);
        float sum = 0.f;
        for (int i = 0; i < PV; i++) sum += expf(sv[i] - m);
        sred[0] = m; sred[1] = logf(sum);
    }
    __syncthreads();
    if (jt < PV) out[(size_t)r * PV + jt] = v - sred[0] - sred[1];
}

// ---------------- word log-softmax in place, one block per row ----------------
__global__ void wlogsoftmax(float* __restrict__ w)
{
    __shared__ float red[256];
    int r = blockIdx.x, tid = threadIdx.x;
    float* row = w + (size_t)r * WV;
    float m = -1e30f;
    for (int i = tid; i < WV; i += 256) m = fmaxf(m, row[i]);
    red[tid] = m; __syncthreads();
    for (int s = 128; s > 0; s >>= 1) { if (tid < s) red[tid] = fmaxf(red[tid], red[tid+s]); __syncthreads(); }
    m = red[0]; __syncthreads();
    float sum = 0.f;
    for (int i = tid; i < WV; i += 256) sum += expf(row[i] - m);
    red[tid] = sum; __syncthreads();
    for (int s = 128; s > 0; s >>= 1) { if (tid < s) red[tid] += red[tid+s]; __syncthreads(); }
    float lg = m + logf(red[0]);
    for (int i = tid; i < WV; i += 256) row[i] -= lg;
}

// ---------------- launch ----------------
extern "C" void kernel_launch(void* const* d_in, const int* in_sizes, int n_in,
                              void* d_out, int out_size)
{
    const int*   pos      = (const int*)d_in[0];
    const int*   word     = (const int*)d_in[1];
    const float* pos_emb  = (const float*)d_in[2];
    const float* word_emb = (const float*)d_in[3];
    const float* pWih     = (const float*)d_in[4];
    const float* pWhh     = (const float*)d_in[5];
    const float* pbih     = (const float*)d_in[6];
    const float* pbhh     = (const float*)d_in[7];
    const float* w0Wih    = (const float*)d_in[8];
    const float* w0Whh    = (const float*)d_in[9];
    const float* w0bih    = (const float*)d_in[10];
    const float* w0bhh    = (const float*)d_in[11];
    const float* w1Wih    = (const float*)d_in[12];
    const float* w1Whh    = (const float*)d_in[13];
    const float* w1bih    = (const float*)d_in[14];
    const float* w1bhh    = (const float*)d_in[15];
    const float* pprojW   = (const float*)d_in[16];
    const float* pprojb   = (const float*)d_in[17];
    const float* wp1W     = (const float*)d_in[18];
    const float* wp1b     = (const float*)d_in[19];
    const float* wp2b     = (const float*)d_in[20];

    float *pA, *pA0, *ph, *wh0, *wh1, *pc, *wc0, *wc1, *wmid;
    cudaGetSymbolAddress((void**)&pA,   g_Apos);
    cudaGetSymbolAddress((void**)&pA0,  g_Aw0);
    cudaGetSymbolAddress((void**)&ph,   g_ph);
    cudaGetSymbolAddress((void**)&wh0,  g_wh0);
    cudaGetSymbolAddress((void**)&wh1,  g_wh1);
    cudaGetSymbolAddress((void**)&pc,   g_pc);
    cudaGetSymbolAddress((void**)&wc0,  g_wc0);
    cudaGetSymbolAddress((void**)&wc1,  g_wc1);
    cudaGetSymbolAddress((void**)&wmid, g_wmid);

    zero_init<<<(Bb*WH + 255) / 256, 256>>>();

    // precompute input projections (+ both biases) for all (t,b) rows
    gemm_nt<<<dim3(4*PH/64, Tt*Bb/64), 256>>>(pos_emb, pos, PE, pWih, PE+WH,
                                              pA, 4*PH, PE, pbih, pbhh);
    gemm_nt<<<dim3(4*WH/64, Tt*Bb/64), 256>>>(word_emb, word, WE, w0Wih, WE+PH,
                                              pA0, 4*WH, WE, w0bih, w0bhh);

    for (int t = 0; t < Tt; t++) {
        const float* ph_p  = ph  + (size_t)t * Bb * PH;
        float*       ph_n  = ph  + (size_t)(t+1) * Bb * PH;
        const float* wh0_p = wh0 + (size_t)t * Bb * WH;
        float*       wh0_n = wh0 + (size_t)(t+1) * Bb * WH;
        const float* wh1_p = wh1 + (size_t)t * Bb * WH;
        float*       wh1_n = wh1 + (size_t)(t+1) * Bb * WH;

        // pos cell: x = [pos_emb ; wh1_prev], recurrent h = ph_prev
        lstm_cell<4><<<PH/4, 128>>>(pA + (size_t)t * Bb * 4 * PH, nullptr, nullptr,
            wh1_p, WH, pWih + PE, PE + WH, WH,
            ph_p,  PH, pWhh,      PH,      PH,
            pc, ph_n, PH);
        // word cell0: x = [word_emb ; ph_new], recurrent h = wh0_prev
        lstm_cell<8><<<WH/8, 256>>>(pA0 + (size_t)t * Bb * 4 * WH, nullptr, nullptr,
            ph_n,  PH, w0Wih + WE, WE + PH, PH,
            wh0_p, WH, w0Whh,      WH,      WH,
            wc0, wh0_n, WH);
        // word cell1: x = wh0_new, recurrent h = wh1_prev
        lstm_cell<8><<<WH/8, 256>>>(nullptr, w1bih, w1bhh,
            wh0_n, WH, w1Wih, WH, WH,
            wh1_p, WH, w1Whh, WH, WH,
            wc1, wh1_n, WH);
    }

    float* out  = (float*)d_out;
    float* wout = out + (size_t)Tt * Bb * PV;

    // w_mid = w_outs @ wp1_W^T + wp1_b
    gemm_nt<<<dim3(WE/64, Tt*Bb/64), 256>>>(wh1 + (size_t)Bb * WH, nullptr, WH,
                                            wp1W, WH, wmid, WE, WH, wp1b, nullptr);
    // word logits = w_mid @ word_emb^T + wp2_b, directly into d_out
    gemm_nt<<<dim3(WV/64, Tt*Bb/64), 256>>>(wmid, nullptr, WE,
                                            word_emb, WE, wout, WV, WE, wp2b, nullptr);
    // pos head (fused log-softmax)
    pos_head<<<Tt*Bb, 64>>>(ph + (size_t)Bb * PH, pprojW, pprojb, out);
    // word log-softmax in place
    wlogsoftmax<<<Tt*Bb, 256>>>(wout);
}

// round 7
// speedup vs baseline: 1.3642x; 1.3642x over previous
#include <cuda_runtime.h>
#include <math.h>

#define Tt 128
#define Bb 32
#define PH 256
#define WH 1024
#define PV 45
#define WV 32000
#define PE 64
#define WE 512

// ---------------- device scratch (no allocations) ----------------
__device__ float g_Apos[Tt*Bb*4*PH];        // [4096][1024] input proj + biases (pos cell)
__device__ float g_Aw0 [Tt*Bb*4*WH];        // [4096][4096] input proj + biases (word cell0)
__device__ float g_ph  [(Tt+1)*Bb*PH];      // pos hidden slots
__device__ float g_wh0 [(Tt+1)*Bb*WH];      // word l0 hidden slots
__device__ float g_wh1 [(Tt+1)*Bb*WH];      // word l1 hidden slots (= w_outs)
__device__ float g_pc  [Bb*PH];
__device__ float g_wc0 [Bb*WH];
__device__ float g_wc1 [Bb*WH];
__device__ float g_wmid[Tt*Bb*WE];          // [4096][512]

// ---------------- packed f32x2 + cp.async helpers ----------------
__device__ __forceinline__ unsigned long long fma2(unsigned long long a,
                                                   unsigned long long b,
                                                   unsigned long long c) {
    unsigned long long d;
    asm("fma.rn.f32x2 %0, %1, %2, %3;" : "=l"(d) : "l"(a), "l"(b), "l"(c));
    return d;
}
__device__ __forceinline__ float acc_sum(unsigned long long v) {
    float x, y;
    asm("mov.b64 {%0,%1}, %2;" : "=f"(x), "=f"(y) : "l"(v));
    return x + y;
}
__device__ __forceinline__ float sigf(float x) { return 1.0f / (1.0f + expf(-x)); }

__device__ __forceinline__ void cp16(void* s, const void* g) {
    unsigned ss = (unsigned)__cvta_generic_to_shared(s);
    asm volatile("cp.async.cg.shared.global [%0], [%1], 16;" :: "r"(ss), "l"(g));
}
__device__ __forceinline__ void cp_commit() {
    asm volatile("cp.async.commit_group;" ::: "memory");
}
template <int N> __device__ __forceinline__ void cp_wait() {
    asm volatile("cp.async.wait_group %0;" :: "n"(N) : "memory");
}

// ---------------- init ----------------
__global__ void zero_init() {
    int i = blockIdx.x * blockDim.x + threadIdx.x;
    if (i < Bb*PH) { g_ph[i] = 0.f; g_pc[i] = 0.f; }
    if (i < Bb*WH) { g_wh0[i] = 0.f; g_wh1[i] = 0.f; g_wc0[i] = 0.f; g_wc1[i] = 0.f; }
}

// ---------------- pipelined NT GEMM ----------------
// C[m,n] = A(gather[m] or m)[0..K) . Bm[n][0..K) + bias1[n] + bias2[n]
// 64x64 tile, BK=16, 256 threads, 4m x 4n per thread, cp.async double buffer.
__global__ __launch_bounds__(256) void gemm_nt(
    const float* __restrict__ A, const int* __restrict__ gather, int lda,
    const float* __restrict__ Bm, int ldb,
    float* __restrict__ C, int ldc, int K,
    const float* __restrict__ bias1, const float* __restrict__ bias2)
{
    __shared__ __align__(16) float As[2][64][20];
    __shared__ __align__(16) float Bs[2][64][20];
    const int tid = threadIdx.x;
    const int m0 = blockIdx.y * 64, n0 = blockIdx.x * 64;
    const int tn = tid & 15, tm = tid >> 4;
    const int lrow = tid >> 2, lks = tid & 3;     // 64 rows x 4 float4 each
    const int agr = gather ? gather[m0 + lrow] : (m0 + lrow);
    const float* aptr = A  + (size_t)agr * lda + lks * 4;
    const float* bptr = Bm + (size_t)(n0 + lrow) * ldb + lks * 4;

    unsigned long long acc[4][4];
#pragma unroll
    for (int r = 0; r < 4; r++)
#pragma unroll
        for (int s = 0; s < 4; s++) acc[r][s] = 0ull;

    const int nch = K >> 4;
    // preload chunk 0
    cp16(&As[0][lrow][lks*4], aptr);
    cp16(&Bs[0][lrow][lks*4], bptr);
    cp_commit();

    for (int ci = 0; ci < nch; ci++) {
        if (ci + 1 < nch) {
            cp16(&As[(ci+1)&1][lrow][lks*4], aptr + (ci+1)*16);
            cp16(&Bs[(ci+1)&1][lrow][lks*4], bptr + (ci+1)*16);
            cp_commit();
            cp_wait<1>();
        } else {
            cp_wait<0>();
        }
        __syncthreads();
        const int bf = ci & 1;
#pragma unroll
        for (int kk = 0; kk < 16; kk += 4) {
            ulonglong2 av[4], bv[4];
#pragma unroll
            for (int r = 0; r < 4; r++) av[r] = *(const ulonglong2*)&As[bf][tm*4 + r][kk];
#pragma unroll
            for (int s = 0; s < 4; s++) bv[s] = *(const ulonglong2*)&Bs[bf][tn + 16*s][kk];
#pragma unroll
            for (int r = 0; r < 4; r++)
#pragma unroll
                for (int s = 0; s < 4; s++) {
                    acc[r][s] = fma2(av[r].x, bv[s].x, acc[r][s]);
                    acc[r][s] = fma2(av[r].y, bv[s].y, acc[r][s]);
                }
        }
        __syncthreads();
    }
#pragma unroll
    for (int s = 0; s < 4; s++) {
        int n = n0 + tn + 16*s;
        float badd = 0.f;
        if (bias1) badd += bias1[n];
        if (bias2) badd += bias2[n];
#pragma unroll
        for (int r = 0; r < 4; r++) {
            int m = m0 + tm*4 + r;
            C[(size_t)m * ldc + n] = acc_sum(acc[r][s]) + badd;
        }
    }
}

// ---------------- pipelined fused LSTM cell ----------------
// gates[b][j] = base(b,j) + x0[b]·W0[j] + x1[b]·W1[j]; j = gate*H + h
// base = pre[b][j] (if pre) else bih[j]+bhh[j]; then pointwise LSTM update.
// CTA: 32 gate cols (8 h x 4 gates, lane = gate col) x RB batch rows.
// Threads = RB*8 (each warp = 4 batch rows). cp.async double buffer, BK=32.
template <int RB>
__global__ void lstm_cell(
    const float* __restrict__ pre,
    const float* __restrict__ bih, const float* __restrict__ bhh,
    const float* __restrict__ x0, int ldx0, const float* __restrict__ W0, int ldW0, int K0,
    const float* __restrict__ x1, int ldx1, const float* __restrict__ W1, int ldW1, int K1,
    float* __restrict__ c_st, float* __restrict__ h_out, int H)
{
    constexpr int NT = RB * 8;
    __shared__ __align__(16) float xs[2][RB][36];
    __shared__ __align__(16) float ws[2][32][36];
    const int tid  = threadIdx.x;
    const int lane = tid & 31;          // gate col within block
    const int wrp  = tid >> 5;          // warp = 4 batch rows
    const int hh   = lane & 7;
    const int gate = lane >> 3;
    const int h    = blockIdx.x * 8 + hh;
    const int j    = gate * H + h;
    const int row0 = blockIdx.y * RB;

    const int nc0 = K0 >> 5, nch = nc0 + (K1 >> 5);
    const int xr = tid >> 3, xks = tid & 7;   // RB*8 == NT x-ops, one each

    unsigned long long acc[4] = {0ull, 0ull, 0ull, 0ull};

    auto load_chunk = [&](int ci, int buf) {
        const float* xp; const float* Wp; int ldx, ldW, k0;
        if (ci < nc0) { xp = x0; Wp = W0; ldx = ldx0; ldW = ldW0; k0 = ci << 5; }
        else          { xp = x1; Wp = W1; ldx = ldx1; ldW = ldW1; k0 = (ci - nc0) << 5; }
        cp16(&xs[buf][xr][xks*4], xp + (size_t)(row0 + xr) * ldx + k0 + xks*4);
#pragma unroll
        for (int o = tid; o < 256; o += NT) {
            int wr = o >> 3, ks = o & 7;
            int jr = (wr >> 3) * H + blockIdx.x * 8 + (wr & 7);
            cp16(&ws[buf][wr][ks*4], Wp + (size_t)jr * ldW + k0 + ks*4);
        }
        cp_commit();
    };

    load_chunk(0, 0);
    for (int ci = 0; ci < nch; ci++) {
        if (ci + 1 < nch) { load_chunk(ci + 1, (ci + 1) & 1); cp_wait<1>(); }
        else              { cp_wait<0>(); }
        __syncthreads();
        const int bf = ci & 1;
#pragma unroll
        for (int kk = 0; kk < 32; kk += 4) {
            ulonglong2 wv = *(const ulonglong2*)&ws[bf][lane][kk];
#pragma unroll
            for (int r = 0; r < 4; r++) {
                ulonglong2 xv = *(const ulonglong2*)&xs[bf][wrp*4 + r][kk];
                acc[r] = fma2(xv.x, wv.x, acc[r]);
                acc[r] = fma2(xv.y, wv.y, acc[r]);
            }
        }
        __syncthreads();
    }

#pragma unroll
    for (int r = 0; r < 4; r++) {
        int b = row0 + wrp*4 + r;
        float v = acc_sum(acc[r]);
        if (pre) v += pre[(size_t)b * (4*H) + j];
        else     v += bih[j] + bhh[j];
        float iv = __shfl_sync(0xffffffffu, v, hh);
        float fv = __shfl_sync(0xffffffffu, v, hh + 8);
        float gv = __shfl_sync(0xffffffffu, v, hh + 16);
        float ov = __shfl_sync(0xffffffffu, v, hh + 24);
        if (gate == 0) {
            float cp = c_st[b*H + h];
            float cn = sigf(fv) * cp + sigf(iv) * tanhf(gv);
            c_st[b*H + h]  = cn;
            h_out[b*H + h] = sigf(ov) * tanhf(cn);
        }
    }
}

// ---------------- pos head: Linear(256->45) + log-softmax ----------------
__global__ void pos_head(const float* __restrict__ pouts,
                         const float* __restrict__ W, const float* __restrict__ bias,
                         float* __restrict__ out)
{
    __shared__ float sv[64];
    __shared__ float sred[2];
    int r = blockIdx.x, jt = threadIdx.x;
    const float* x = pouts + (size_t)r * PH;
    float v = 0.f;
    if (jt < PV) {
        float s = bias[jt];
        const float* w = W + (size_t)jt * PH;
#pragma unroll 4
        for (int k = 0; k < PH; k++) s += x[k] * w[k];
        v = s;
    }
    sv[jt] = v;
    __syncthreads();
    if (jt == 0) {
        float m = sv[0];
        for (int i = 1; i < PV; i++) m = fmaxf(m, sv[i]);
        float sum = 0.f;
        for (int i = 0; i < PV; i++) sum += expf(sv[i] - m);
        sred[0] = m; sred[1] = logf(sum);
    }
    __syncthreads();
    if (jt < PV) out[(size_t)r * PV + jt] = v - sred[0] - sred[1];
}

// ---------------- word log-softmax in place ----------------
__global__ void wlogsoftmax(float* __restrict__ w)
{
    __shared__ float red[256];
    int r = blockIdx.x, tid = threadIdx.x;
    float* row = w + (size_t)r * WV;
    float m = -1e30f;
    for (int i = tid; i < WV; i += 256) m = fmaxf(m, row[i]);
    red[tid] = m; __syncthreads();
    for (int s = 128; s > 0; s >>= 1) { if (tid < s) red[tid] = fmaxf(red[tid], red[tid+s]); __syncthreads(); }
    m = red[0]; __syncthreads();
    float sum = 0.f;
    for (int i = tid; i < WV; i += 256) sum += expf(row[i] - m);
    red[tid] = sum; __syncthreads();
    for (int s = 128; s > 0; s >>= 1) { if (tid < s) red[tid] += red[tid+s]; __syncthreads(); }
    float lg = m + logf(red[0]);
    for (int i = tid; i < WV; i += 256) row[i] -= lg;
}

// ---------------- launch ----------------
extern "C" void kernel_launch(void* const* d_in, const int* in_sizes, int n_in,
                              void* d_out, int out_size)
{
    const int*   pos      = (const int*)d_in[0];
    const int*   word     = (const int*)d_in[1];
    const float* pos_emb  = (const float*)d_in[2];
    const float* word_emb = (const float*)d_in[3];
    const float* pWih     = (const float*)d_in[4];
    const float* pWhh     = (const float*)d_in[5];
    const float* pbih     = (const float*)d_in[6];
    const float* pbhh     = (const float*)d_in[7];
    const float* w0Wih    = (const float*)d_in[8];
    const float* w0Whh    = (const float*)d_in[9];
    const float* w0bih    = (const float*)d_in[10];
    const float* w0bhh    = (const float*)d_in[11];
    const float* w1Wih    = (const float*)d_in[12];
    const float* w1Whh    = (const float*)d_in[13];
    const float* w1bih    = (const float*)d_in[14];
    const float* w1bhh    = (const float*)d_in[15];
    const float* pprojW   = (const float*)d_in[16];
    const float* pprojb   = (const float*)d_in[17];
    const float* wp1W     = (const float*)d_in[18];
    const float* wp1b     = (const float*)d_in[19];
    const float* wp2b     = (const float*)d_in[20];

    float *pA, *pA0, *ph, *wh0, *wh1, *pc, *wc0, *wc1, *wmid;
    cudaGetSymbolAddress((void**)&pA,   g_Apos);
    cudaGetSymbolAddress((void**)&pA0,  g_Aw0);
    cudaGetSymbolAddress((void**)&ph,   g_ph);
    cudaGetSymbolAddress((void**)&wh0,  g_wh0);
    cudaGetSymbolAddress((void**)&wh1,  g_wh1);
    cudaGetSymbolAddress((void**)&pc,   g_pc);
    cudaGetSymbolAddress((void**)&wc0,  g_wc0);
    cudaGetSymbolAddress((void**)&wc1,  g_wc1);
    cudaGetSymbolAddress((void**)&wmid, g_wmid);

    zero_init<<<(Bb*WH + 255) / 256, 256>>>();

    // precompute input projections (+ both biases) for all (t,b) rows
    gemm_nt<<<dim3(4*PH/64, Tt*Bb/64), 256>>>(pos_emb, pos, PE, pWih, PE+WH,
                                              pA, 4*PH, PE, pbih, pbhh);
    gemm_nt<<<dim3(4*WH/64, Tt*Bb/64), 256>>>(word_emb, word, WE, w0Wih, WE+PH,
                                              pA0, 4*WH, WE, w0bih, w0bhh);

    for (int t = 0; t < Tt; t++) {
        const float* ph_p  = ph  + (size_t)t * Bb * PH;
        float*       ph_n  = ph  + (size_t)(t+1) * Bb * PH;
        const float* wh0_p = wh0 + (size_t)t * Bb * WH;
        float*       wh0_n = wh0 + (size_t)(t+1) * Bb * WH;
        const float* wh1_p = wh1 + (size_t)t * Bb * WH;
        float*       wh1_n = wh1 + (size_t)(t+1) * Bb * WH;

        // pos cell: x = [pos_emb ; wh1_prev], recurrent h = ph_prev
        lstm_cell<8><<<dim3(PH/8, 4), 64>>>(pA + (size_t)t * Bb * 4 * PH, nullptr, nullptr,
            wh1_p, WH, pWih + PE, PE + WH, WH,
            ph_p,  PH, pWhh,      PH,      PH,
            pc, ph_n, PH);
        // word cell0: x = [word_emb ; ph_new], recurrent h = wh0_prev
        lstm_cell<32><<<dim3(WH/8, 1), 256>>>(pA0 + (size_t)t * Bb * 4 * WH, nullptr, nullptr,
            ph_n,  PH, w0Wih + WE, WE + PH, PH,
            wh0_p, WH, w0Whh,      WH,      WH,
            wc0, wh0_n, WH);
        // word cell1: x = wh0_new, recurrent h = wh1_prev
        lstm_cell<32><<<dim3(WH/8, 1), 256>>>(nullptr, w1bih, w1bhh,
            wh0_n, WH, w1Wih, WH, WH,
            wh1_p, WH, w1Whh, WH, WH,
            wc1, wh1_n, WH);
    }

    float* out  = (float*)d_out;
    float* wout = out + (size_t)Tt * Bb * PV;

    // w_mid = w_outs @ wp1_W^T + wp1_b
    gemm_nt<<<dim3(WE/64, Tt*Bb/64), 256>>>(wh1 + (size_t)Bb * WH, nullptr, WH,
                                            wp1W, WH, wmid, WE, WH, wp1b, nullptr);
    // word logits = w_mid @ word_emb^T + wp2_b, directly into d_out
    gemm_nt<<<dim3(WV/64, Tt*Bb/64), 256>>>(wmid, nullptr, WE,
                                            word_emb, WE, wout, WV, WE, wp2b, nullptr);
    // pos head (fused log-softmax)
    pos_head<<<Tt*Bb, 64>>>(ph + (size_t)Bb * PH, pprojW, pprojb, out);
    // word log-softmax in place
    wlogsoftmax<<<Tt*Bb, 256>>>(wout);
}

// round 9
// speedup vs baseline: 1.3786x; 1.0106x over previous
#include <cuda_runtime.h>
#include <math.h>

#define Tt 128
#define Bb 32
#define PH 256
#define WH 1024
#define PV 45
#define WV 32000
#define PE 64
#define WE 512

// ---------------- device scratch (no allocations) ----------------
__device__ float g_Apos[Tt*Bb*4*PH];        // [4096][1024] input proj + biases (pos cell)
__device__ float g_Aw0 [Tt*Bb*4*WH];        // [4096][4096] input proj + biases (word cell0)
__device__ float g_ph  [(Tt+1)*Bb*PH];      // pos hidden slots
__device__ float g_wh0 [(Tt+1)*Bb*WH];      // word l0 hidden slots
__device__ float g_wh1 [(Tt+1)*Bb*WH];      // word l1 hidden slots (= w_outs)
__device__ float g_pc  [Bb*PH];
__device__ float g_wc0 [Bb*WH];
__device__ float g_wc1 [Bb*WH];
__device__ float g_wmid[Tt*Bb*WE];          // [4096][512]

// ---------------- packed f32x2 + cp.async helpers ----------------
__device__ __forceinline__ unsigned long long fma2(unsigned long long a,
                                                   unsigned long long b,
                                                   unsigned long long c) {
    unsigned long long d;
    asm("fma.rn.f32x2 %0, %1, %2, %3;" : "=l"(d) : "l"(a), "l"(b), "l"(c));
    return d;
}
__device__ __forceinline__ float acc_sum(unsigned long long v) {
    float x, y;
    asm("mov.b64 {%0,%1}, %2;" : "=f"(x), "=f"(y) : "l"(v));
    return x + y;
}
__device__ __forceinline__ float sigf(float x) { return 1.0f / (1.0f + expf(-x)); }

__device__ __forceinline__ void cp16(void* s, const void* g) {
    unsigned ss = (unsigned)__cvta_generic_to_shared(s);
    asm volatile("cp.async.cg.shared.global [%0], [%1], 16;" :: "r"(ss), "l"(g));
}
__device__ __forceinline__ void cp_commit() {
    asm volatile("cp.async.commit_group;" ::: "memory");
}
template <int N> __device__ __forceinline__ void cp_wait() {
    asm volatile("cp.async.wait_group %0;" :: "n"(N) : "memory");
}

// ---------------- init ----------------
__global__ void zero_init() {
    int i = blockIdx.x * blockDim.x + threadIdx.x;
    if (i < Bb*PH) { g_ph[i] = 0.f; g_pc[i] = 0.f; }
    if (i < Bb*WH) { g_wh0[i] = 0.f; g_wh1[i] = 0.f; g_wc0[i] = 0.f; g_wc1[i] = 0.f; }
}

// ---------------- 4-stage pipelined NT GEMM ----------------
// C[m,n] = A(gather[m] or m)[0..K) . Bm[n][0..K) + bias1[n] + bias2[n]
// 64x64 tile, BK=16, 256 threads, 4m x 4n per thread, k-packed f32x2.
__global__ __launch_bounds__(256) void gemm_nt(
    const float* __restrict__ A, const int* __restrict__ gather, int lda,
    const float* __restrict__ Bm, int ldb,
    float* __restrict__ C, int ldc, int K,
    const float* __restrict__ bias1, const float* __restrict__ bias2)
{
    constexpr int S = 4;
    __shared__ __align__(16) float As[S][64][20];
    __shared__ __align__(16) float Bs[S][64][20];
    const int tid = threadIdx.x;
    const int m0 = blockIdx.y * 64, n0 = blockIdx.x * 64;
    const int tn = tid & 15, tm = tid >> 4;
    const int lrow = tid >> 2, lks = tid & 3;     // 64 rows x 4 float4 each
    const int agr = gather ? gather[m0 + lrow] : (m0 + lrow);
    const float* aptr = A  + (size_t)agr * lda + lks * 4;
    const float* bptr = Bm + (size_t)(n0 + lrow) * ldb + lks * 4;

    unsigned long long acc[4][4];
#pragma unroll
    for (int r = 0; r < 4; r++)
#pragma unroll
        for (int s = 0; s < 4; s++) acc[r][s] = 0ull;

    const int nch = K >> 4;
#pragma unroll
    for (int i = 0; i < S - 1; i++) {
        if (i < nch) {
            cp16(&As[i][lrow][lks*4], aptr + i*16);
            cp16(&Bs[i][lrow][lks*4], bptr + i*16);
        }
        cp_commit();
    }

    for (int ci = 0; ci < nch; ci++) {
        if (ci + S - 1 < nch) {
            const int b = (ci + S - 1) & (S - 1);
            cp16(&As[b][lrow][lks*4], aptr + (ci + S - 1)*16);
            cp16(&Bs[b][lrow][lks*4], bptr + (ci + S - 1)*16);
            cp_commit();
            cp_wait<S-1>();
        } else {
            cp_wait<0>();
        }
        __syncthreads();
        const int bf = ci & (S - 1);
#pragma unroll
        for (int kk = 0; kk < 16; kk += 4) {
            ulonglong2 av[4], bv[4];
#pragma unroll
            for (int r = 0; r < 4; r++) av[r] = *(const ulonglong2*)&As[bf][tm*4 + r][kk];
#pragma unroll
            for (int s = 0; s < 4; s++) bv[s] = *(const ulonglong2*)&Bs[bf][tn + 16*s][kk];
#pragma unroll
            for (int r = 0; r < 4; r++)
#pragma unroll
                for (int s = 0; s < 4; s++) {
                    acc[r][s] = fma2(av[r].x, bv[s].x, acc[r][s]);
                    acc[r][s] = fma2(av[r].y, bv[s].y, acc[r][s]);
                }
        }
        __syncthreads();
    }
#pragma unroll
    for (int s = 0; s < 4; s++) {
        int n = n0 + tn + 16*s;
        float badd = 0.f;
        if (bias1) badd += bias1[n];
        if (bias2) badd += bias2[n];
#pragma unroll
        for (int r = 0; r < 4; r++) {
            int m = m0 + tm*4 + r;
            C[(size_t)m * ldc + n] = acc_sum(acc[r][s]) + badd;
        }
    }
}

// ---------------- 4-stage pipelined fused LSTM cell ----------------
// gates[b][j] = base(b,j) + x0[b]·W0[j] + x1[b]·W1[j]; j = gate*H + h
// base = pre[b][j] (if pre) else bih[j]+bhh[j]; then pointwise LSTM update.
// CTA: 32 gate cols (8 h x 4 gates, lane = gate col) x RB batch rows.
// Threads = RB*8 (each warp = 4 batch rows). BK=32.
template <int RB>
__global__ void lstm_cell(
    const float* __restrict__ pre,
    const float* __restrict__ bih, const float* __restrict__ bhh,
    const float* __restrict__ x0, int ldx0, const float* __restrict__ W0, int ldW0, int K0,
    const float* __restrict__ x1, int ldx1, const float* __restrict__ W1, int ldW1, int K1,
    float* __restrict__ c_st, float* __restrict__ h_out, int H)
{
    constexpr int NT = RB * 8;
    constexpr int S  = 4;
    __shared__ __align__(16) float xs[S][RB][36];
    __shared__ __align__(16) float ws[S][32][36];
    const int tid  = threadIdx.x;
    const int lane = tid & 31;          // gate col within block
    const int wrp  = tid >> 5;          // warp = 4 batch rows
    const int hh   = lane & 7;
    const int gate = lane >> 3;
    const int h    = blockIdx.x * 8 + hh;
    const int j    = gate * H + h;
    const int row0 = blockIdx.y * RB;

    const int nc0 = K0 >> 5, nch = nc0 + (K1 >> 5);
    const int xr = tid >> 3, xks = tid & 7;   // RB*8 == NT x-ops, one each

    unsigned long long acc[4] = {0ull, 0ull, 0ull, 0ull};

    auto load_chunk = [&](int ci, int buf) {
        const float* xp; const float* Wp; int ldx, ldW, k0;
        if (ci < nc0) { xp = x0; Wp = W0; ldx = ldx0; ldW = ldW0; k0 = ci << 5; }
        else          { xp = x1; Wp = W1; ldx = ldx1; ldW = ldW1; k0 = (ci - nc0) << 5; }
        cp16(&xs[buf][xr][xks*4], xp + (size_t)(row0 + xr) * ldx + k0 + xks*4);
#pragma unroll
        for (int o = tid; o < 256; o += NT) {
            int wr = o >> 3, ks = o & 7;
            int jr = (wr >> 3) * H + blockIdx.x * 8 + (wr & 7);
            cp16(&ws[buf][wr][ks*4], Wp + (size_t)jr * ldW + k0 + ks*4);
        }
        cp_commit();
    };

#pragma unroll
    for (int i = 0; i < S - 1; i++) {
        if (i < nch) load_chunk(i, i);
        else cp_commit();
    }

    for (int ci = 0; ci < nch; ci++) {
        if (ci + S - 1 < nch) {
            load_chunk(ci + S - 1, (ci + S - 1) & (S - 1));
            cp_wait<S-1>();
        } else {
            cp_wait<0>();
        }
        __syncthreads();
        const int bf = ci & (S - 1);
#pragma unroll
        for (int kk = 0; kk < 32; kk += 4) {
            ulonglong2 wv = *(const ulonglong2*)&ws[bf][lane][kk];
#pragma unroll
            for (int r = 0; r < 4; r++) {
                ulonglong2 xv = *(const ulonglong2*)&xs[bf][wrp*4 + r][kk];
                acc[r] = fma2(xv.x, wv.x, acc[r]);
                acc[r] = fma2(xv.y, wv.y, acc[r]);
            }
        }
        __syncthreads();
    }

#pragma unroll
    for (int r = 0; r < 4; r++) {
        int b = row0 + wrp*4 + r;
        float v = acc_sum(acc[r]);
        if (pre) v += pre[(size_t)b * (4*H) + j];
        else     v += bih[j] + bhh[j];
        float iv = __shfl_sync(0xffffffffu, v, hh);
        float fv = __shfl_sync(0xffffffffu, v, hh + 8);
        float gv = __shfl_sync(0xffffffffu, v, hh + 16);
        float ov = __shfl_sync(0xffffffffu, v, hh + 24);
        if (gate == 0) {
            float cp = c_st[b*H + h];
            float cn = sigf(fv) * cp + sigf(iv) * tanhf(gv);
            c_st[b*H + h]  = cn;
            h_out[b*H + h] = sigf(ov) * tanhf(cn);
        }
    }
}

// ---------------- pos head: Linear(256->45) + log-softmax ----------------
__global__ void pos_head(const float* __restrict__ pouts,
                         const float* __restrict__ W, const float* __restrict__ bias,
                         float* __restrict__ out)
{
    __shared__ float sv[64];
    __shared__ float sred[2];
    int r = blockIdx.x, jt = threadIdx.x;
    const float* x = pouts + (size_t)r * PH;
    float v = 0.f;
    if (jt < PV) {
        float s = bias[jt];
        const float* w = W + (size_t)jt * PH;
#pragma unroll 4
        for (int k = 0; k < PH; k++) s += x[k] * w[k];
        v = s;
    }
    sv[jt] = v;
    __syncthreads();
    if (jt == 0) {
        float m = sv[0];
        for (int i = 1; i < PV; i++) m = fmaxf(m, sv[i]);
        float sum = 0.f;
        for (int i = 0; i < PV; i++) sum += expf(sv[i] - m);
        sred[0] = m; sred[1] = logf(sum);
    }
    __syncthreads();
    if (jt < PV) out[(size_t)r * PV + jt] = v - sred[0] - sred[1];
}

// ---------------- word log-softmax in place (vectorized) ----------------
__global__ __launch_bounds__(512) void wlogsoftmax(float* __restrict__ w)
{
    __shared__ float red[512];
    int r = blockIdx.x, tid = threadIdx.x;
    float4* row = (float4*)(w + (size_t)r * WV);
    const int NV = WV / 4;           // 8000 float4 per row
    float m = -1e30f;
    for (int i = tid; i < NV; i += 512) {
        float4 v = row[i];
        m = fmaxf(m, fmaxf(fmaxf(v.x, v.y), fmaxf(v.z, v.w)));
    }
    red[tid] = m; __syncthreads();
    for (int s = 256; s > 0; s >>= 1) { if (tid < s) red[tid] = fmaxf(red[tid], red[tid+s]); __syncthreads(); }
    m = red[0]; __syncthreads();
    float sum = 0.f;
    for (int i = tid; i < NV; i += 512) {
        float4 v = row[i];
        sum += expf(v.x - m) + expf(v.y - m) + expf(v.z - m) + expf(v.w - m);
    }
    red[tid] = sum; __syncthreads();
    for (int s = 256; s > 0; s >>= 1) { if (tid < s) red[tid] += red[tid+s]; __syncthreads(); }
    float lg = m + logf(red[0]);
    for (int i = tid; i < NV; i += 512) {
        float4 v = row[i];
        v.x -= lg; v.y -= lg; v.z -= lg; v.w -= lg;
        row[i] = v;
    }
}

// ---------------- launch ----------------
extern "C" void kernel_launch(void* const* d_in, const int* in_sizes, int n_in,
                              void* d_out, int out_size)
{
    const int*   pos      = (const int*)d_in[0];
    const int*   word     = (const int*)d_in[1];
    const float* pos_emb  = (const float*)d_in[2];
    const float* word_emb = (const float*)d_in[3];
    const float* pWih     = (const float*)d_in[4];
    const float* pWhh     = (const float*)d_in[5];
    const float* pbih     = (const float*)d_in[6];
    const float* pbhh     = (const float*)d_in[7];
    const float* w0Wih    = (const float*)d_in[8];
    const float* w0Whh    = (const float*)d_in[9];
    const float* w0bih    = (const float*)d_in[10];
    const float* w0bhh    = (const float*)d_in[11];
    const float* w1Wih    = (const float*)d_in[12];
    const float* w1Whh    = (const float*)d_in[13];
    const float* w1bih    = (const float*)d_in[14];
    const float* w1bhh    = (const float*)d_in[15];
    const float* pprojW   = (const float*)d_in[16];
    const float* pprojb   = (const float*)d_in[17];
    const float* wp1W     = (const float*)d_in[18];
    const float* wp1b     = (const float*)d_in[19];
    const float* wp2b     = (const float*)d_in[20];

    float *pA, *pA0, *ph, *wh0, *wh1, *pc, *wc0, *wc1, *wmid;
    cudaGetSymbolAddress((void**)&pA,   g_Apos);
    cudaGetSymbolAddress((void**)&pA0,  g_Aw0);
    cudaGetSymbolAddress((void**)&ph,   g_ph);
    cudaGetSymbolAddress((void**)&wh0,  g_wh0);
    cudaGetSymbolAddress((void**)&wh1,  g_wh1);
    cudaGetSymbolAddress((void**)&pc,   g_pc);
    cudaGetSymbolAddress((void**)&wc0,  g_wc0);
    cudaGetSymbolAddress((void**)&wc1,  g_wc1);
    cudaGetSymbolAddress((void**)&wmid, g_wmid);

    zero_init<<<(Bb*WH + 255) / 256, 256>>>();

    // precompute input projections (+ both biases) for all (t,b) rows
    gemm_nt<<<dim3(4*PH/64, Tt*Bb/64), 256>>>(pos_emb, pos, PE, pWih, PE+WH,
                                              pA, 4*PH, PE, pbih, pbhh);
    gemm_nt<<<dim3(4*WH/64, Tt*Bb/64), 256>>>(word_emb, word, WE, w0Wih, WE+PH,
                                              pA0, 4*WH, WE, w0bih, w0bhh);

    for (int t = 0; t < Tt; t++) {
        const float* ph_p  = ph  + (size_t)t * Bb * PH;
        float*       ph_n  = ph  + (size_t)(t+1) * Bb * PH;
        const float* wh0_p = wh0 + (size_t)t * Bb * WH;
        float*       wh0_n = wh0 + (size_t)(t+1) * Bb * WH;
        const float* wh1_p = wh1 + (size_t)t * Bb * WH;
        float*       wh1_n = wh1 + (size_t)(t+1) * Bb * WH;

        // pos cell: x = [pos_emb ; wh1_prev], recurrent h = ph_prev
        lstm_cell<16><<<dim3(PH/8, 2), 128>>>(pA + (size_t)t * Bb * 4 * PH, nullptr, nullptr,
            wh1_p, WH, pWih + PE, PE + WH, WH,
            ph_p,  PH, pWhh,      PH,      PH,
            pc, ph_n, PH);
        // word cell0: x = [word_emb ; ph_new], recurrent h = wh0_prev
        lstm_cell<32><<<dim3(WH/8, 1), 256>>>(pA0 + (size_t)t * Bb * 4 * WH, nullptr, nullptr,
            ph_n,  PH, w0Wih + WE, WE + PH, PH,
            wh0_p, WH, w0Whh,      WH,      WH,
            wc0, wh0_n, WH);
        // word cell1: x = wh0_new, recurrent h = wh1_prev
        lstm_cell<32><<<dim3(WH/8, 1), 256>>>(nullptr, w1bih, w1bhh,
            wh0_n, WH, w1Wih, WH, WH,
            wh1_p, WH, w1Whh, WH, WH,
            wc1, wh1_n, WH);
    }

    float* out  = (float*)d_out;
    float* wout = out + (size_t)Tt * Bb * PV;

    // w_mid = w_outs @ wp1_W^T + wp1_b
    gemm_nt<<<dim3(WE/64, Tt*Bb/64), 256>>>(wh1 + (size_t)Bb * WH, nullptr, WH,
                                            wp1W, WH, wmid, WE, WH, wp1b, nullptr);
    // word logits = w_mid @ word_emb^T + wp2_b, directly into d_out
    gemm_nt<<<dim3(WV/64, Tt*Bb/64), 256>>>(wmid, nullptr, WE,
                                            word_emb, WE, wout, WV, WE, wp2b, nullptr);
    // pos head (fused log-softmax)
    pos_head<<<Tt*Bb, 64>>>(ph + (size_t)Bb * PH, pprojW, pprojb, out);
    // word log-softmax in place
    wlogsoftmax<<<Tt*Bb, 512>>>(wout);
}

// round 10
// speedup vs baseline: 1.4532x; 1.0541x over previous
#include <cuda_runtime.h>
#include <math.h>

#define Tt 128
#define Bb 32
#define PH 256
#define WH 1024
#define PV 45
#define WV 32000
#define PE 64
#define WE 512

// ---------------- device scratch (no allocations) ----------------
__device__ float g_Apos[Tt*Bb*4*PH];        // [4096][1024] input proj + biases (pos cell)
__device__ float g_Aw0 [Tt*Bb*4*WH];        // [4096][4096] input proj + biases (word cell0)
__device__ float g_ph  [(Tt+1)*Bb*PH];      // pos hidden slots
__device__ float g_wh0 [(Tt+1)*Bb*WH];      // word l0 hidden slots
__device__ float g_wh1 [(Tt+1)*Bb*WH];      // word l1 hidden slots (= w_outs)
__device__ float g_pc  [Bb*PH];
__device__ float g_wc0 [Bb*WH];
__device__ float g_wc1 [Bb*WH];
__device__ float g_wmid[Tt*Bb*WE];          // [4096][512]

// ---------------- packed f32x2 + cp.async helpers ----------------
__device__ __forceinline__ unsigned long long fma2(unsigned long long a,
                                                   unsigned long long b,
                                                   unsigned long long c) {
    unsigned long long d;
    asm("fma.rn.f32x2 %0, %1, %2, %3;" : "=l"(d) : "l"(a), "l"(b), "l"(c));
    return d;
}
__device__ __forceinline__ float acc_sum(unsigned long long v) {
    float x, y;
    asm("mov.b64 {%0,%1}, %2;" : "=f"(x), "=f"(y) : "l"(v));
    return x + y;
}
__device__ __forceinline__ float sigf(float x) { return 1.0f / (1.0f + expf(-x)); }

__device__ __forceinline__ void cp16(void* s, const void* g) {
    unsigned ss = (unsigned)__cvta_generic_to_shared(s);
    asm volatile("cp.async.cg.shared.global [%0], [%1], 16;" :: "r"(ss), "l"(g));
}
__device__ __forceinline__ void cp_commit() {
    asm volatile("cp.async.commit_group;" ::: "memory");
}
template <int N> __device__ __forceinline__ void cp_wait() {
    asm volatile("cp.async.wait_group %0;" :: "n"(N) : "memory");
}
__device__ __forceinline__ void half_bar(int id) {
    asm volatile("bar.sync %0, 128;" :: "r"(id) : "memory");
}

// ---------------- init ----------------
__global__ void zero_init() {
    int i = blockIdx.x * blockDim.x + threadIdx.x;
    if (i < Bb*PH) { g_ph[i] = 0.f; g_pc[i] = 0.f; }
    if (i < Bb*WH) { g_wh0[i] = 0.f; g_wh1[i] = 0.f; g_wc0[i] = 0.f; g_wc1[i] = 0.f; }
}

// ---------------- 4-stage pipelined NT GEMM (unchanged structure) ----------------
__global__ __launch_bounds__(256) void gemm_nt(
    const float* __restrict__ A, const int* __restrict__ gather, int lda,
    const float* __restrict__ Bm, int ldb,
    float* __restrict__ C, int ldc, int K,
    const float* __restrict__ bias1, const float* __restrict__ bias2)
{
    constexpr int S = 4;
    __shared__ __align__(16) float As[S][64][20];
    __shared__ __align__(16) float Bs[S][64][20];
    const int tid = threadIdx.x;
    const int m0 = blockIdx.y * 64, n0 = blockIdx.x * 64;
    const int tn = tid & 15, tm = tid >> 4;
    const int lrow = tid >> 2, lks = tid & 3;
    const int agr = gather ? gather[m0 + lrow] : (m0 + lrow);
    const float* aptr = A  + (size_t)agr * lda + lks * 4;
    const float* bptr = Bm + (size_t)(n0 + lrow) * ldb + lks * 4;

    unsigned long long acc[4][4];
#pragma unroll
    for (int r = 0; r < 4; r++)
#pragma unroll
        for (int s = 0; s < 4; s++) acc[r][s] = 0ull;

    const int nch = K >> 4;
#pragma unroll
    for (int i = 0; i < S - 1; i++) {
        if (i < nch) {
            cp16(&As[i][lrow][lks*4], aptr + i*16);
            cp16(&Bs[i][lrow][lks*4], bptr + i*16);
        }
        cp_commit();
    }

    for (int ci = 0; ci < nch; ci++) {
        if (ci + S - 1 < nch) {
            const int b = (ci + S - 1) & (S - 1);
            cp16(&As[b][lrow][lks*4], aptr + (ci + S - 1)*16);
            cp16(&Bs[b][lrow][lks*4], bptr + (ci + S - 1)*16);
            cp_commit();
            cp_wait<S-1>();
        } else {
            cp_wait<0>();
        }
        __syncthreads();
        const int bf = ci & (S - 1);
#pragma unroll
        for (int kk = 0; kk < 16; kk += 4) {
            ulonglong2 av[4], bv[4];
#pragma unroll
            for (int r = 0; r < 4; r++) av[r] = *(const ulonglong2*)&As[bf][tm*4 + r][kk];
#pragma unroll
            for (int s = 0; s < 4; s++) bv[s] = *(const ulonglong2*)&Bs[bf][tn + 16*s][kk];
#pragma unroll
            for (int r = 0; r < 4; r++)
#pragma unroll
                for (int s = 0; s < 4; s++) {
                    acc[r][s] = fma2(av[r].x, bv[s].x, acc[r][s]);
                    acc[r][s] = fma2(av[r].y, bv[s].y, acc[r][s]);
                }
        }
        __syncthreads();
    }
#pragma unroll
    for (int s = 0; s < 4; s++) {
        int n = n0 + tn + 16*s;
        float badd = 0.f;
        if (bias1) badd += bias1[n];
        if (bias2) badd += bias2[n];
#pragma unroll
        for (int r = 0; r < 4; r++) {
            int m = m0 + tm*4 + r;
            C[(size_t)m * ldc + n] = acc_sum(acc[r][s]) + badd;
        }
    }
}

// ---------------- k-split dual-pipeline fused LSTM cell ----------------
// 256 threads. Warps 0-3 = k-half 0, warps 4-7 = k-half 1; each half runs an
// independent cp.async pipeline (per-thread groups) + named barrier, so each
// SMSP has 2 active warps. Each warp accumulates RPW batch rows (acc[RPW]).
// Partial sums combined through smem, then pointwise LSTM on half 0.
// RB = 4*RPW rows per CTA; lane = gate col (8 h x 4 gates); BK=32; S=4.
template <int RPW>
__global__ __launch_bounds__(256) void lstm_cell2(
    const float* __restrict__ pre,
    const float* __restrict__ bih, const float* __restrict__ bhh,
    const float* __restrict__ x0, int ldx0, const float* __restrict__ W0, int ldW0, int K0,
    const float* __restrict__ x1, int ldx1, const float* __restrict__ W1, int ldW1, int K1,
    float* __restrict__ c_st, float* __restrict__ h_out, int H)
{
    constexpr int RB = 4 * RPW;
    constexpr int S  = 4;
    constexpr int HALF = S * (RB + 32) * 36;   // floats per half
    extern __shared__ float smem[];
    const int tid  = threadIdx.x;
    const int lane = tid & 31;
    const int wrp  = tid >> 5;
    const int half = wrp >> 2;        // k-half
    const int wl   = wrp & 3;         // warp within half
    const int lt   = tid & 127;       // thread within half
    const int hh   = lane & 7;
    const int gate = lane >> 3;
    const int h    = blockIdx.x * 8 + hh;
    const int j    = gate * H + h;
    const int rowB = blockIdx.y * RB;

    float* xs = smem + half * HALF;           // [S][RB][36]
    float* ws = xs + S * RB * 36;             // [S][32][36]

    const int nc0 = K0 >> 5;
    const int nch = nc0 + (K1 >> 5);
    const int nchH = nch >> 1;
    const int cbase = half * nchH;

    unsigned long long acc[RPW];
#pragma unroll
    for (int r = 0; r < RPW; r++) acc[r] = 0ull;

    auto load_chunk = [&](int cl, int buf) {
        const int ci = cbase + cl;
        const float* xp; const float* Wp; int ldx, ldW, k0;
        if (ci < nc0) { xp = x0; Wp = W0; ldx = ldx0; ldW = ldW0; k0 = ci << 5; }
        else          { xp = x1; Wp = W1; ldx = ldx1; ldW = ldW1; k0 = (ci - nc0) << 5; }
        for (int o = lt; o < RB * 8; o += 128) {
            int row = o >> 3, ks = o & 7;
            cp16(&xs[(buf*RB + row)*36 + ks*4],
                 xp + (size_t)(rowB + row) * ldx + k0 + ks*4);
        }
#pragma unroll
        for (int o = lt; o < 256; o += 128) {
            int wr = o >> 3, ks = o & 7;
            int jr = (wr >> 3) * H + blockIdx.x * 8 + (wr & 7);
            cp16(&ws[(buf*32 + wr)*36 + ks*4],
                 Wp + (size_t)jr * ldW + k0 + ks*4);
        }
        cp_commit();
    };

#pragma unroll
    for (int i = 0; i < S - 1; i++) {
        if (i < nchH) load_chunk(i, i);
        else cp_commit();
    }

    for (int cl = 0; cl < nchH; cl++) {
        if (cl + S - 1 < nchH) {
            load_chunk(cl + S - 1, (cl + S - 1) & (S - 1));
            cp_wait<S-1>();
        } else {
            cp_wait<0>();
        }
        half_bar(1 + half);
        const int bf = cl & (S - 1);
        const float* wsb = &ws[(bf*32 + lane)*36];
        const float* xsb = &xs[bf*RB*36];
#pragma unroll
        for (int kk = 0; kk < 32; kk += 4) {
            ulonglong2 wv = *(const ulonglong2*)(wsb + kk);
#pragma unroll
            for (int r = 0; r < RPW; r++) {
                ulonglong2 xv = *(const ulonglong2*)(xsb + (wl*RPW + r)*36 + kk);
                acc[r] = fma2(xv.x, wv.x, acc[r]);
                acc[r] = fma2(xv.y, wv.y, acc[r]);
            }
        }
        half_bar(1 + half);
    }

    // combine k-halves: half 1 writes partial sums, half 0 adds + pointwise
    __syncthreads();
    float* red = smem;                         // overlay, loads are all done
    if (half == 1) {
#pragma unroll
        for (int r = 0; r < RPW; r++)
            red[(wl*32 + lane)*RPW + r] = acc_sum(acc[r]);
    }
    __syncthreads();
    if (half == 0) {
#pragma unroll
        for (int r = 0; r < RPW; r++) {
            int b = rowB + wl*RPW + r;
            float v = acc_sum(acc[r]) + red[(wl*32 + lane)*RPW + r];
            if (pre) v += pre[(size_t)b * (4*H) + j];
            else     v += bih[j] + bhh[j];
            float iv = __shfl_sync(0xffffffffu, v, hh);
            float fv = __shfl_sync(0xffffffffu, v, hh + 8);
            float gv = __shfl_sync(0xffffffffu, v, hh + 16);
            float ov = __shfl_sync(0xffffffffu, v, hh + 24);
            if (gate == 0) {
                float cp = c_st[b*H + h];
                float cn = sigf(fv) * cp + sigf(iv) * tanhf(gv);
                c_st[b*H + h]  = cn;
                h_out[b*H + h] = sigf(ov) * tanhf(cn);
            }
        }
    }
}

// ---------------- pos head: Linear(256->45) + log-softmax ----------------
__global__ void pos_head(const float* __restrict__ pouts,
                         const float* __restrict__ W, const float* __restrict__ bias,
                         float* __restrict__ out)
{
    __shared__ float sv[64];
    __shared__ float sred[2];
    int r = blockIdx.x, jt = threadIdx.x;
    const float* x = pouts + (size_t)r * PH;
    float v = 0.f;
    if (jt < PV) {
        float s = bias[jt];
        const float* w = W + (size_t)jt * PH;
#pragma unroll 4
        for (int k = 0; k < PH; k++) s += x[k] * w[k];
        v = s;
    }
    sv[jt] = v;
    __syncthreads();
    if (jt == 0) {
        float m = sv[0];
        for (int i = 1; i < PV; i++) m = fmaxf(m, sv[i]);
        float sum = 0.f;
        for (int i = 0; i < PV; i++) sum += expf(sv[i] - m);
        sred[0] = m; sred[1] = logf(sum);
    }
    __syncthreads();
    if (jt < PV) out[(size_t)r * PV + jt] = v - sred[0] - sred[1];
}

// ---------------- word log-softmax in place (vectorized) ----------------
__global__ __launch_bounds__(512) void wlogsoftmax(float* __restrict__ w)
{
    __shared__ float red[512];
    int r = blockIdx.x, tid = threadIdx.x;
    float4* row = (float4*)(w + (size_t)r * WV);
    const int NV = WV / 4;
    float m = -1e30f;
    for (int i = tid; i < NV; i += 512) {
        float4 v = row[i];
        m = fmaxf(m, fmaxf(fmaxf(v.x, v.y), fmaxf(v.z, v.w)));
    }
    red[tid] = m; __syncthreads();
    for (int s = 256; s > 0; s >>= 1) { if (tid < s) red[tid] = fmaxf(red[tid], red[tid+s]); __syncthreads(); }
    m = red[0]; __syncthreads();
    float sum = 0.f;
    for (int i = tid; i < NV; i += 512) {
        float4 v = row[i];
        sum += expf(v.x - m) + expf(v.y - m) + expf(v.z - m) + expf(v.w - m);
    }
    red[tid] = sum; __syncthreads();
    for (int s = 256; s > 0; s >>= 1) { if (tid < s) red[tid] += red[tid+s]; __syncthreads(); }
    float lg = m + logf(red[0]);
    for (int i = tid; i < NV; i += 512) {
        float4 v = row[i];
        v.x -= lg; v.y -= lg; v.z -= lg; v.w -= lg;
        row[i] = v;
    }
}

// ---------------- launch ----------------
extern "C" void kernel_launch(void* const* d_in, const int* in_sizes, int n_in,
                              void* d_out, int out_size)
{
    const int*   pos      = (const int*)d_in[0];
    const int*   word     = (const int*)d_in[1];
    const float* pos_emb  = (const float*)d_in[2];
    const float* word_emb = (const float*)d_in[3];
    const float* pWih     = (const float*)d_in[4];
    const float* pWhh     = (const float*)d_in[5];
    const float* pbih     = (const float*)d_in[6];
    const float* pbhh     = (const float*)d_in[7];
    const float* w0Wih    = (const float*)d_in[8];
    const float* w0Whh    = (const float*)d_in[9];
    const float* w0bih    = (const float*)d_in[10];
    const float* w0bhh    = (const float*)d_in[11];
    const float* w1Wih    = (const float*)d_in[12];
    const float* w1Whh    = (const float*)d_in[13];
    const float* w1bih    = (const float*)d_in[14];
    const float* w1bhh    = (const float*)d_in[15];
    const float* pprojW   = (const float*)d_in[16];
    const float* pprojb   = (const float*)d_in[17];
    const float* wp1W     = (const float*)d_in[18];
    const float* wp1b     = (const float*)d_in[19];
    const float* wp2b     = (const float*)d_in[20];

    float *pA, *pA0, *ph, *wh0, *wh1, *pc, *wc0, *wc1, *wmid;
    cudaGetSymbolAddress((void**)&pA,   g_Apos);
    cudaGetSymbolAddress((void**)&pA0,  g_Aw0);
    cudaGetSymbolAddress((void**)&ph,   g_ph);
    cudaGetSymbolAddress((void**)&wh0,  g_wh0);
    cudaGetSymbolAddress((void**)&wh1,  g_wh1);
    cudaGetSymbolAddress((void**)&pc,   g_pc);
    cudaGetSymbolAddress((void**)&wc0,  g_wc0);
    cudaGetSymbolAddress((void**)&wc1,  g_wc1);
    cudaGetSymbolAddress((void**)&wmid, g_wmid);

    // dynamic smem sizes: S*(RB+32)*36 floats per half, 2 halves
    const int smem_pos = 2 * 4 * (16 + 32) * 36 * 4;   // RPW=4 -> 55296 B
    const int smem_w   = 2 * 4 * (32 + 32) * 36 * 4;   // RPW=8 -> 73728 B
    cudaFuncSetAttribute(lstm_cell2<4>, cudaFuncAttributeMaxDynamicSharedMemorySize, smem_pos);
    cudaFuncSetAttribute(lstm_cell2<8>, cudaFuncAttributeMaxDynamicSharedMemorySize, smem_w);

    zero_init<<<(Bb*WH + 255) / 256, 256>>>();

    // precompute input projections (+ both biases) for all (t,b) rows
    gemm_nt<<<dim3(4*PH/64, Tt*Bb/64), 256>>>(pos_emb, pos, PE, pWih, PE+WH,
                                              pA, 4*PH, PE, pbih, pbhh);
    gemm_nt<<<dim3(4*WH/64, Tt*Bb/64), 256>>>(word_emb, word, WE, w0Wih, WE+PH,
                                              pA0, 4*WH, WE, w0bih, w0bhh);

    for (int t = 0; t < Tt; t++) {
        const float* ph_p  = ph  + (size_t)t * Bb * PH;
        float*       ph_n  = ph  + (size_t)(t+1) * Bb * PH;
        const float* wh0_p = wh0 + (size_t)t * Bb * WH;
        float*       wh0_n = wh0 + (size_t)(t+1) * Bb * WH;
        const float* wh1_p = wh1 + (size_t)t * Bb * WH;
        float*       wh1_n = wh1 + (size_t)(t+1) * Bb * WH;

        // pos cell: x = [pos_emb ; wh1_prev], recurrent h = ph_prev
        lstm_cell2<4><<<dim3(PH/8, 2), 256, smem_pos>>>(
            pA + (size_t)t * Bb * 4 * PH, nullptr, nullptr,
            wh1_p, WH, pWih + PE, PE + WH, WH,
            ph_p,  PH, pWhh,      PH,      PH,
            pc, ph_n, PH);
        // word cell0: x = [word_emb ; ph_new], recurrent h = wh0_prev
        lstm_cell2<8><<<dim3(WH/8, 1), 256, smem_w>>>(
            pA0 + (size_t)t * Bb * 4 * WH, nullptr, nullptr,
            ph_n,  PH, w0Wih + WE, WE + PH, PH,
            wh0_p, WH, w0Whh,      WH,      WH,
            wc0, wh0_n, WH);
        // word cell1: x = wh0_new, recurrent h = wh1_prev
        lstm_cell2<8><<<dim3(WH/8, 1), 256, smem_w>>>(
            nullptr, w1bih, w1bhh,
            wh0_n, WH, w1Wih, WH, WH,
            wh1_p, WH, w1Whh, WH, WH,
            wc1, wh1_n, WH);
    }

    float* out  = (float*)d_out;
    float* wout = out + (size_t)Tt * Bb * PV;

    // w_mid = w_outs @ wp1_W^T + wp1_b
    gemm_nt<<<dim3(WE/64, Tt*Bb/64), 256>>>(wh1 + (size_t)Bb * WH, nullptr, WH,
                                            wp1W, WH, wmid, WE, WH, wp1b, nullptr);
    // word logits = w_mid @ word_emb^T + wp2_b, directly into d_out
    gemm_nt<<<dim3(WV/64, Tt*Bb/64), 256>>>(wmid, nullptr, WE,
                                            word_emb, WE, wout, WV, WE, wp2b, nullptr);
    // pos head (fused log-softmax)
    pos_head<<<Tt*Bb, 64>>>(ph + (size_t)Bb * PH, pprojW, pprojb, out);
    // word log-softmax in place
    wlogsoftmax<<<Tt*Bb, 512>>>(wout);
}

// round 11
// speedup vs baseline: 1.5153x; 1.0427x over previous
#include <cuda_runtime.h>
#include <math.h>

#define Tt 128
#define Bb 32
#define PH 256
#define WH 1024
#define PV 45
#define WV 32000
#define PE 64
#define WE 512
#define GRID 128

// ---------------- device scratch (no allocations) ----------------
__device__ float g_Apos[Tt*Bb*4*PH];
__device__ float g_Aw0 [Tt*Bb*4*WH];
__device__ float g_ph  [(Tt+1)*Bb*PH];
__device__ float g_wh0 [(Tt+1)*Bb*WH];
__device__ float g_wh1 [(Tt+1)*Bb*WH];
__device__ float g_pc  [Bb*PH];
__device__ float g_wc0 [Bb*WH];
__device__ float g_wc1 [Bb*WH];
__device__ float g_wmid[Tt*Bb*WE];
__device__ unsigned g_bar;

// ---------------- helpers ----------------
__device__ __forceinline__ unsigned long long fma2(unsigned long long a,
                                                   unsigned long long b,
                                                   unsigned long long c) {
    unsigned long long d;
    asm("fma.rn.f32x2 %0, %1, %2, %3;" : "=l"(d) : "l"(a), "l"(b), "l"(c));
    return d;
}
__device__ __forceinline__ float acc_sum(unsigned long long v) {
    float x, y;
    asm("mov.b64 {%0,%1}, %2;" : "=f"(x), "=f"(y) : "l"(v));
    return x + y;
}
__device__ __forceinline__ float sigf(float x) { return 1.0f / (1.0f + expf(-x)); }

__device__ __forceinline__ void cp16(void* s, const void* g) {
    unsigned ss = (unsigned)__cvta_generic_to_shared(s);
    asm volatile("cp.async.cg.shared.global [%0], [%1], 16;" :: "r"(ss), "l"(g));
}
__device__ __forceinline__ void cp_commit() {
    asm volatile("cp.async.commit_group;" ::: "memory");
}
template <int N> __device__ __forceinline__ void cp_wait() {
    asm volatile("cp.async.wait_group %0;" :: "n"(N) : "memory");
}

// grid-wide barrier (all GRID CTAs co-resident by construction)
__device__ __forceinline__ void gsync(unsigned& phase) {
    __syncthreads();
    if (threadIdx.x == 0) {
        __threadfence();
        atomicAdd(&g_bar, 1u);
        unsigned want = (++phase) * (unsigned)GRID;
        while (atomicAdd(&g_bar, 0u) < want) __nanosleep(100);
    }
    __syncthreads();
}

// ---------------- init ----------------
__global__ void zero_init() {
    int i = blockIdx.x * blockDim.x + threadIdx.x;
    if (i == 0) g_bar = 0u;
    if (i < Bb*PH) { g_ph[i] = 0.f; g_pc[i] = 0.f; }
    if (i < Bb*WH) { g_wh0[i] = 0.f; g_wh1[i] = 0.f; g_wc0[i] = 0.f; g_wc1[i] = 0.f; }
}

// ---------------- 4-stage pipelined NT GEMM ----------------
__global__ __launch_bounds__(256) void gemm_nt(
    const float* __restrict__ A, const int* __restrict__ gather, int lda,
    const float* __restrict__ Bm, int ldb,
    float* __restrict__ C, int ldc, int K,
    const float* __restrict__ bias1, const float* __restrict__ bias2)
{
    constexpr int S = 4;
    __shared__ __align__(16) float As[S][64][20];
    __shared__ __align__(16) float Bs[S][64][20];
    const int tid = threadIdx.x;
    const int m0 = blockIdx.y * 64, n0 = blockIdx.x * 64;
    const int tn = tid & 15, tm = tid >> 4;
    const int lrow = tid >> 2, lks = tid & 3;
    const int agr = gather ? gather[m0 + lrow] : (m0 + lrow);
    const float* aptr = A  + (size_t)agr * lda + lks * 4;
    const float* bptr = Bm + (size_t)(n0 + lrow) * ldb + lks * 4;

    unsigned long long acc[4][4];
#pragma unroll
    for (int r = 0; r < 4; r++)
#pragma unroll
        for (int s = 0; s < 4; s++) acc[r][s] = 0ull;

    const int nch = K >> 4;
#pragma unroll
    for (int i = 0; i < S - 1; i++) {
        if (i < nch) {
            cp16(&As[i][lrow][lks*4], aptr + i*16);
            cp16(&Bs[i][lrow][lks*4], bptr + i*16);
        }
        cp_commit();
    }

    for (int ci = 0; ci < nch; ci++) {
        if (ci + S - 1 < nch) {
            const int b = (ci + S - 1) & (S - 1);
            cp16(&As[b][lrow][lks*4], aptr + (ci + S - 1)*16);
            cp16(&Bs[b][lrow][lks*4], bptr + (ci + S - 1)*16);
            cp_commit();
            cp_wait<S-1>();
        } else {
            cp_wait<0>();
        }
        __syncthreads();
        const int bf = ci & (S - 1);
#pragma unroll
        for (int kk = 0; kk < 16; kk += 4) {
            ulonglong2 av[4], bv[4];
#pragma unroll
            for (int r = 0; r < 4; r++) av[r] = *(const ulonglong2*)&As[bf][tm*4 + r][kk];
#pragma unroll
            for (int s = 0; s < 4; s++) bv[s] = *(const ulonglong2*)&Bs[bf][tn + 16*s][kk];
#pragma unroll
            for (int r = 0; r < 4; r++)
#pragma unroll
                for (int s = 0; s < 4; s++) {
                    acc[r][s] = fma2(av[r].x, bv[s].x, acc[r][s]);
                    acc[r][s] = fma2(av[r].y, bv[s].y, acc[r][s]);
                }
        }
        __syncthreads();
    }
#pragma unroll
    for (int s = 0; s < 4; s++) {
        int n = n0 + tn + 16*s;
        float badd = 0.f;
        if (bias1) badd += bias1[n];
        if (bias2) badd += bias2[n];
#pragma unroll
        for (int r = 0; r < 4; r++) {
            int m = m0 + tm*4 + r;
            C[(size_t)m * ldc + n] = acc_sum(acc[r][s]) + badd;
        }
    }
}

// ---------------- one LSTM cell phase (inside persistent kernel) ----------------
// CTA cta covers h-cols [cta*8, cta*8+8) x 4 gates x all 32 batch rows.
// 512 threads = 2 k-halves x 8 warps; each warp 4 batch rows; lane = gate col.
// 4-stage cp.async pipeline per half; named barrier per half; 2-way k-reduce.
__device__ __noinline__ void cell_phase(
    float* smem,
    const float* pre, const float* bih, const float* bhh,
    const float* x0, int ldx0, const float* W0, int ldW0, int K0,
    const float* x1, int ldx1, const float* W1, int ldW1, int K1,
    float* c_st, float* h_out, int H)
{
    constexpr int S = 4;
    constexpr int HALF = S * 64 * 36;     // floats per half (xs 32 rows + ws 32 cols)
    const int cta = blockIdx.x;
    if (cta * 8 >= H) return;             // inactive CTA (pos phase): whole CTA skips
    const int tid  = threadIdx.x;
    const int lane = tid & 31;
    const int wrp  = tid >> 5;
    const int half = wrp >> 3;
    const int wl   = wrp & 7;
    const int lt   = tid & 255;
    const int hh   = lane & 7;
    const int gate = lane >> 3;
    const int h    = cta * 8 + hh;
    const int j    = gate * H + h;

    float* xs = smem + half * HALF;       // [S][32][36]
    float* ws = xs + S * 32 * 36;         // [S][32][36]

    const int nc0  = K0 >> 5;
    const int nch  = nc0 + (K1 >> 5);
    const int nchH = nch >> 1;
    const int cbase = half * nchH;

    unsigned long long acc[4] = {0ull, 0ull, 0ull, 0ull};

    const int lrow = lt >> 3, lks = lt & 7;       // 32 rows/cols x 8 float4
    const int ljr  = (lrow >> 3) * H + cta * 8 + (lrow & 7);

    auto load_chunk = [&](int cl, int buf) {
        const int ci = cbase + cl;
        const float* xp; const float* Wp; int ldx, ldW, k0;
        if (ci < nc0) { xp = x0; Wp = W0; ldx = ldx0; ldW = ldW0; k0 = ci << 5; }
        else          { xp = x1; Wp = W1; ldx = ldx1; ldW = ldW1; k0 = (ci - nc0) << 5; }
        cp16(&xs[(buf*32 + lrow)*36 + lks*4], xp + (size_t)lrow * ldx + k0 + lks*4);
        cp16(&ws[(buf*32 + lrow)*36 + lks*4], Wp + (size_t)ljr  * ldW + k0 + lks*4);
        cp_commit();
    };

#pragma unroll
    for (int i = 0; i < S - 1; i++) load_chunk(i, i);

    for (int cl = 0; cl < nchH; cl++) {
        if (cl + S - 1 < nchH) { load_chunk(cl + S - 1, (cl + S - 1) & (S - 1)); cp_wait<S-1>(); }
        else                   { cp_wait<0>(); }
        asm volatile("bar.sync %0, 256;" :: "r"(1 + half) : "memory");
        const int bf = cl & (S - 1);
        const float* wsb = &ws[(bf*32 + lane)*36];
        const float* xsb = &xs[(bf*32 + wl*4)*36];
#pragma unroll
        for (int kk = 0; kk < 32; kk += 4) {
            ulonglong2 wv = *(const ulonglong2*)(wsb + kk);
#pragma unroll
            for (int r = 0; r < 4; r++) {
                ulonglong2 xv = *(const ulonglong2*)(xsb + r*36 + kk);
                acc[r] = fma2(xv.x, wv.x, acc[r]);
                acc[r] = fma2(xv.y, wv.y, acc[r]);
            }
        }
        asm volatile("bar.sync %0, 256;" :: "r"(1 + half) : "memory");
    }

    // 2-way k-reduction through smem, then pointwise on half 0
    __syncthreads();
    float4* red = (float4*)smem;          // overlay: all pipeline reads done
    if (half == 1) {
        float4 p;
        p.x = acc_sum(acc[0]); p.y = acc_sum(acc[1]);
        p.z = acc_sum(acc[2]); p.w = acc_sum(acc[3]);
        red[wl*32 + lane] = p;
    }
    __syncthreads();
    if (half == 0) {
        float4 p = red[wl*32 + lane];
        float vs[4] = {p.x, p.y, p.z, p.w};
#pragma unroll
        for (int r = 0; r < 4; r++) {
            int b = wl*4 + r;
            float v = acc_sum(acc[r]) + vs[r];
            if (pre) v += pre[(size_t)b * (4*H) + j];
            else     v += bih[j] + bhh[j];
            float iv = __shfl_sync(0xffffffffu, v, hh);
            float fv = __shfl_sync(0xffffffffu, v, hh + 8);
            float gv = __shfl_sync(0xffffffffu, v, hh + 16);
            float ov = __shfl_sync(0xffffffffu, v, hh + 24);
            if (gate == 0) {
                float cp = c_st[b*H + h];
                float cn = sigf(fv) * cp + sigf(iv) * tanhf(gv);
                c_st[b*H + h]  = cn;
                h_out[b*H + h] = sigf(ov) * tanhf(cn);
            }
        }
    }
}

// ---------------- persistent recurrence kernel ----------------
__global__ __launch_bounds__(512, 1) void recurrence(
    const float* __restrict__ pre_pos, const float* __restrict__ pre_w0,
    const float* __restrict__ pWih,  const float* __restrict__ pWhh,
    const float* __restrict__ w0Wih, const float* __restrict__ w0Whh,
    const float* __restrict__ w1Wih, const float* __restrict__ w1Whh,
    const float* __restrict__ w1bih, const float* __restrict__ w1bhh)
{
    extern __shared__ float smem[];
    unsigned phase = 0;
    for (int t = 0; t < Tt; t++) {
        // pos cell: x = [pos_emb ; wh1_prev] (pre) + recurrent ph_prev
        cell_phase(smem, pre_pos + (size_t)t * Bb * 4 * PH, nullptr, nullptr,
                   g_wh1 + (size_t)t * Bb * WH, WH, pWih + PE, PE + WH, WH,
                   g_ph  + (size_t)t * Bb * PH, PH, pWhh,      PH,      PH,
                   g_pc, g_ph + (size_t)(t+1) * Bb * PH, PH);
        gsync(phase);
        // word cell0: x = [word_emb ; ph_new] (pre) + recurrent wh0_prev
        cell_phase(smem, pre_w0 + (size_t)t * Bb * 4 * WH, nullptr, nullptr,
                   g_ph  + (size_t)(t+1) * Bb * PH, PH, w0Wih + WE, WE + PH, PH,
                   g_wh0 + (size_t)t * Bb * WH,     WH, w0Whh,      WH,      WH,
                   g_wc0, g_wh0 + (size_t)(t+1) * Bb * WH, WH);
        gsync(phase);
        // word cell1: x = wh0_new + recurrent wh1_prev
        cell_phase(smem, nullptr, w1bih, w1bhh,
                   g_wh0 + (size_t)(t+1) * Bb * WH, WH, w1Wih, WH, WH,
                   g_wh1 + (size_t)t * Bb * WH,     WH, w1Whh, WH, WH,
                   g_wc1, g_wh1 + (size_t)(t+1) * Bb * WH, WH);
        gsync(phase);
    }
}

// ---------------- pos head: Linear(256->45) + log-softmax ----------------
__global__ void pos_head(const float* __restrict__ pouts,
                         const float* __restrict__ W, const float* __restrict__ bias,
                         float* __restrict__ out)
{
    __shared__ float sv[64];
    __shared__ float sred[2];
    int r = blockIdx.x, jt = threadIdx.x;
    const float* x = pouts + (size_t)r * PH;
    float v = 0.f;
    if (jt < PV) {
        float s = bias[jt];
        const float* w = W + (size_t)jt * PH;
#pragma unroll 4
        for (int k = 0; k < PH; k++) s += x[k] * w[k];
        v = s;
    }
    sv[jt] = v;
    __syncthreads();
    if (jt == 0) {
        float m = sv[0];
        for (int i = 1; i < PV; i++) m = fmaxf(m, sv[i]);
        float sum = 0.f;
        for (int i = 0; i < PV; i++) sum += expf(sv[i] - m);
        sred[0] = m; sred[1] = logf(sum);
    }
    __syncthreads();
    if (jt < PV) out[(size_t)r * PV + jt] = v - sred[0] - sred[1];
}

// ---------------- word log-softmax in place (vectorized) ----------------
__global__ __launch_bounds__(512) void wlogsoftmax(float* __restrict__ w)
{
    __shared__ float red[512];
    int r = blockIdx.x, tid = threadIdx.x;
    float4* row = (float4*)(w + (size_t)r * WV);
    const int NV = WV / 4;
    float m = -1e30f;
    for (int i = tid; i < NV; i += 512) {
        float4 v = row[i];
        m = fmaxf(m, fmaxf(fmaxf(v.x, v.y), fmaxf(v.z, v.w)));
    }
    red[tid] = m; __syncthreads();
    for (int s = 256; s > 0; s >>= 1) { if (tid < s) red[tid] = fmaxf(red[tid], red[tid+s]); __syncthreads(); }
    m = red[0]; __syncthreads();
    float sum = 0.f;
    for (int i = tid; i < NV; i += 512) {
        float4 v = row[i];
        sum += expf(v.x - m) + expf(v.y - m) + expf(v.z - m) + expf(v.w - m);
    }
    red[tid] = sum; __syncthreads();
    for (int s = 256; s > 0; s >>= 1) { if (tid < s) red[tid] += red[tid+s]; __syncthreads(); }
    float lg = m + logf(red[0]);
    for (int i = tid; i < NV; i += 512) {
        float4 v = row[i];
        v.x -= lg; v.y -= lg; v.z -= lg; v.w -= lg;
        row[i] = v;
    }
}

// ---------------- launch ----------------
extern "C" void kernel_launch(void* const* d_in, const int* in_sizes, int n_in,
                              void* d_out, int out_size)
{
    const int*   pos      = (const int*)d_in[0];
    const int*   word     = (const int*)d_in[1];
    const float* pos_emb  = (const float*)d_in[2];
    const float* word_emb = (const float*)d_in[3];
    const float* pWih     = (const float*)d_in[4];
    const float* pWhh     = (const float*)d_in[5];
    const float* pbih     = (const float*)d_in[6];
    const float* pbhh     = (const float*)d_in[7];
    const float* w0Wih    = (const float*)d_in[8];
    const float* w0Whh    = (const float*)d_in[9];
    const float* w0bih    = (const float*)d_in[10];
    const float* w0bhh    = (const float*)d_in[11];
    const float* w1Wih    = (const float*)d_in[12];
    const float* w1Whh    = (const float*)d_in[13];
    const float* w1bih    = (const float*)d_in[14];
    const float* w1bhh    = (const float*)d_in[15];
    const float* pprojW   = (const float*)d_in[16];
    const float* pprojb   = (const float*)d_in[17];
    const float* wp1W     = (const float*)d_in[18];
    const float* wp1b     = (const float*)d_in[19];
    const float* wp2b     = (const float*)d_in[20];

    float *pA, *pA0, *ph, *wh1, *wmid;
    cudaGetSymbolAddress((void**)&pA,   g_Apos);
    cudaGetSymbolAddress((void**)&pA0,  g_Aw0);
    cudaGetSymbolAddress((void**)&ph,   g_ph);
    cudaGetSymbolAddress((void**)&wh1,  g_wh1);
    cudaGetSymbolAddress((void**)&wmid, g_wmid);

    const int smem_rec = 2 * 4 * 64 * 36 * 4;   // 73728 B
    static int attr_done = 0;
    cudaFuncSetAttribute(recurrence, cudaFuncAttributeMaxDynamicSharedMemorySize, smem_rec);
    (void)attr_done;

    zero_init<<<(Bb*WH + 255) / 256, 256>>>();

    // precompute input projections (+ both biases) for all (t,b) rows
    gemm_nt<<<dim3(4*PH/64, Tt*Bb/64), 256>>>(pos_emb, pos, PE, pWih, PE+WH,
                                              pA, 4*PH, PE, pbih, pbhh);
    gemm_nt<<<dim3(4*WH/64, Tt*Bb/64), 256>>>(word_emb, word, WE, w0Wih, WE+PH,
                                              pA0, 4*WH, WE, w0bih, w0bhh);

    // whole recurrence in one persistent kernel
    recurrence<<<GRID, 512, smem_rec>>>(pA, pA0, pWih, pWhh,
                                        w0Wih, w0Whh, w1Wih, w1Whh,
                                        w1bih, w1bhh);

    float* out  = (float*)d_out;
    float* wout = out + (size_t)Tt * Bb * PV;

    // w_mid = w_outs @ wp1_W^T + wp1_b
    gemm_nt<<<dim3(WE/64, Tt*Bb/64), 256>>>(wh1 + (size_t)Bb * WH, nullptr, WH,
                                            wp1W, WH, wmid, WE, WH, wp1b, nullptr);
    // word logits = w_mid @ word_emb^T + wp2_b, directly into d_out
    gemm_nt<<<dim3(WV/64, Tt*Bb/64), 256>>>(wmid, nullptr, WE,
                                            word_emb, WE, wout, WV, WE, wp2b, nullptr);
    // pos head (fused log-softmax)
    pos_head<<<Tt*Bb, 64>>>(ph + (size_t)Bb * PH, pprojW, pprojb, out);
    // word log-softmax in place
    wlogsoftmax<<<Tt*Bb, 512>>>(wout);
}

// round 12
// speedup vs baseline: 2.0431x; 1.3483x over previous
#include <cuda_runtime.h>
#include <math.h>

#define Tt 128
#define Bb 32
#define PH 256
#define WH 1024
#define PV 45
#define WV 32000
#define PE 64
#define WE 512
#define GRID 128

// ---------------- device scratch (no allocations) ----------------
__device__ float g_Apos[Tt*Bb*4*PH];
__device__ float g_Aw0 [Tt*Bb*4*WH];
__device__ float g_ph  [(Tt+1)*Bb*PH];
__device__ float g_wh0 [(Tt+1)*Bb*WH];
__device__ float g_wh1 [(Tt+1)*Bb*WH];
__device__ float g_pc  [Bb*PH];
__device__ float g_wc0 [Bb*WH];
__device__ float g_wc1 [Bb*WH];
__device__ float g_wmid[Tt*Bb*WE];
__device__ unsigned g_cnt;
__device__ volatile unsigned g_gen;

// ---------------- helpers ----------------
__device__ __forceinline__ unsigned long long fma2(unsigned long long a,
                                                   unsigned long long b,
                                                   unsigned long long c) {
    unsigned long long d;
    asm("fma.rn.f32x2 %0, %1, %2, %3;" : "=l"(d) : "l"(a), "l"(b), "l"(c));
    return d;
}
__device__ __forceinline__ float acc_sum(unsigned long long v) {
    float x, y;
    asm("mov.b64 {%0,%1}, %2;" : "=f"(x), "=f"(y) : "l"(v));
    return x + y;
}
__device__ __forceinline__ float sigf(float x) { return 1.0f / (1.0f + expf(-x)); }

__device__ __forceinline__ void cp16(void* s, const void* g) {
    unsigned ss = (unsigned)__cvta_generic_to_shared(s);
    asm volatile("cp.async.cg.shared.global [%0], [%1], 16;" :: "r"(ss), "l"(g));
}
__device__ __forceinline__ void cp_commit() {
    asm volatile("cp.async.commit_group;" ::: "memory");
}
template <int N> __device__ __forceinline__ void cp_wait() {
    asm volatile("cp.async.wait_group %0;" :: "n"(N) : "memory");
}

// sense-reversing grid barrier (all GRID CTAs co-resident: 1 CTA/SM, 128 <= 148)
__device__ __forceinline__ void gsync() {
    __syncthreads();
    if (threadIdx.x == 0) {
        unsigned gen = g_gen;
        __threadfence();
        if (atomicAdd(&g_cnt, 1u) == GRID - 1u) {
            g_cnt = 0u;
            __threadfence();
            g_gen = gen + 1u;
        } else {
            while (g_gen == gen) { }
        }
        __threadfence();
    }
    __syncthreads();
}

// ---------------- init ----------------
__global__ void zero_init() {
    int i = blockIdx.x * blockDim.x + threadIdx.x;
    if (i == 0) { g_cnt = 0u; g_gen = 0u; }
    if (i < Bb*PH) { g_ph[i] = 0.f; g_pc[i] = 0.f; }
    if (i < Bb*WH) { g_wh0[i] = 0.f; g_wh1[i] = 0.f; g_wc0[i] = 0.f; g_wc1[i] = 0.f; }
}

// ---------------- 4-stage pipelined NT GEMM ----------------
__global__ __launch_bounds__(256) void gemm_nt(
    const float* __restrict__ A, const int* __restrict__ gather, int lda,
    const float* __restrict__ Bm, int ldb,
    float* __restrict__ C, int ldc, int K,
    const float* __restrict__ bias1, const float* __restrict__ bias2)
{
    constexpr int S = 4;
    __shared__ __align__(16) float As[S][64][20];
    __shared__ __align__(16) float Bs[S][64][20];
    const int tid = threadIdx.x;
    const int m0 = blockIdx.y * 64, n0 = blockIdx.x * 64;
    const int tn = tid & 15, tm = tid >> 4;
    const int lrow = tid >> 2, lks = tid & 3;
    const int agr = gather ? gather[m0 + lrow] : (m0 + lrow);
    const float* aptr = A  + (size_t)agr * lda + lks * 4;
    const float* bptr = Bm + (size_t)(n0 + lrow) * ldb + lks * 4;

    unsigned long long acc[4][4];
#pragma unroll
    for (int r = 0; r < 4; r++)
#pragma unroll
        for (int s = 0; s < 4; s++) acc[r][s] = 0ull;

    const int nch = K >> 4;
#pragma unroll
    for (int i = 0; i < S - 1; i++) {
        if (i < nch) {
            cp16(&As[i][lrow][lks*4], aptr + i*16);
            cp16(&Bs[i][lrow][lks*4], bptr + i*16);
        }
        cp_commit();
    }

    for (int ci = 0; ci < nch; ci++) {
        if (ci + S - 1 < nch) {
            const int b = (ci + S - 1) & (S - 1);
            cp16(&As[b][lrow][lks*4], aptr + (ci + S - 1)*16);
            cp16(&Bs[b][lrow][lks*4], bptr + (ci + S - 1)*16);
            cp_commit();
            cp_wait<S-1>();
        } else {
            cp_wait<0>();
        }
        __syncthreads();
        const int bf = ci & (S - 1);
#pragma unroll
        for (int kk = 0; kk < 16; kk += 4) {
            ulonglong2 av[4], bv[4];
#pragma unroll
            for (int r = 0; r < 4; r++) av[r] = *(const ulonglong2*)&As[bf][tm*4 + r][kk];
#pragma unroll
            for (int s = 0; s < 4; s++) bv[s] = *(const ulonglong2*)&Bs[bf][tn + 16*s][kk];
#pragma unroll
            for (int r = 0; r < 4; r++)
#pragma unroll
                for (int s = 0; s < 4; s++) {
                    acc[r][s] = fma2(av[r].x, bv[s].x, acc[r][s]);
                    acc[r][s] = fma2(av[r].y, bv[s].y, acc[r][s]);
                }
        }
        __syncthreads();
    }
#pragma unroll
    for (int s = 0; s < 4; s++) {
        int n = n0 + tn + 16*s;
        float badd = 0.f;
        if (bias1) badd += bias1[n];
        if (bias2) badd += bias2[n];
#pragma unroll
        for (int r = 0; r < 4; r++) {
            int m = m0 + tm*4 + r;
            C[(size_t)m * ldc + n] = acc_sum(acc[r][s]) + badd;
        }
    }
}

// ---------------- LSTM cell phase: outer-product warps + 8-way k-split ----------------
// CTA cta owns gate cols [32 cols]: 8 h-cols x 4 gates. 256 threads = 8 warps.
// Each warp owns the FULL 32x32 C tile over its k-region (nch/8 chunks of 32k);
// lane = rg(8 row-groups) x cg(4 col-groups); thread tile 4 rows x 8 cols.
// smem: xs/ws [2 stages][8 warps][32 rows][32 floats, XOR-swizzled].
// Deterministic 8-way reduction + pointwise at the end.
__device__ __noinline__ void cell_phase(
    float* smem,
    const float* pre, const float* bih, const float* bhh,
    const float* x0, int ldx0, const float* W0, int ldW0, int K0,
    const float* x1, int ldx1, const float* W1, int ldW1, int K1,
    float* c_st, float* h_out, int H)
{
    const int cta = blockIdx.x;
    if (cta * 8 >= H) return;
    const int tid  = threadIdx.x;
    const int lane = tid & 31;
    const int wid  = tid >> 5;
    const int rg   = lane >> 2;       // row group 0..7 (rows rg*4..rg*4+3)
    const int cg   = lane & 3;        // col group 0..3 (cols cg*8..cg*8+7)

    float* xs = smem;                  // [2][8][32][32]
    float* ws = smem + 2*8*32*32;      // [2][8][32][32]

    const int nc0 = K0 >> 5;
    const int nch = nc0 + (K1 >> 5);
    const int cpw = nch >> 3;          // chunks per warp

    // preload pre/bias for this thread's pointwise element (b, h)
    const int pb = tid >> 3, phh = tid & 7;
    const int hmy = cta * 8 + phh;
    float pv[4];
#pragma unroll
    for (int gt = 0; gt < 4; gt++) {
        if (pre) pv[gt] = pre[(size_t)pb * (4*H) + gt*H + hmy];
        else     pv[gt] = bih[gt*H + hmy] + bhh[gt*H + hmy];
    }

    unsigned long long acc[4][8];
#pragma unroll
    for (int r = 0; r < 4; r++)
#pragma unroll
        for (int c = 0; c < 8; c++) acc[r][c] = 0ull;

    auto load_stage = [&](int st, int cs) {
#pragma unroll
        for (int i = 0; i < 8; i++) {
            int idx = tid + (i << 8);          // 0..2047
            int wslot = idx >> 8;
            int rem = idx & 255;
            int row = rem >> 3, ks = rem & 7;
            int ci = wslot * cpw + cs;
            const float* xp; const float* Wp; int ldx, ldW, k0;
            if (ci < nc0) { xp = x0; Wp = W0; ldx = ldx0; ldW = ldW0; k0 = ci << 5; }
            else          { xp = x1; Wp = W1; ldx = ldx1; ldW = ldW1; k0 = (ci - nc0) << 5; }
            cp16(&xs[((st*8 + wslot)*32 + row)*32 + ((ks ^ (row >> 2)) << 2)],
                 xp + (size_t)row * ldx + k0 + (ks << 2));
            int jr = (row >> 3) * H + cta * 8 + (row & 7);   // row as col index
            cp16(&ws[((st*8 + wslot)*32 + row)*32 + ((ks ^ (row >> 3)) << 2)],
                 Wp + (size_t)jr * ldW + k0 + (ks << 2));
        }
        cp_commit();
    };

    load_stage(0, 0);
    for (int cs = 0; cs < cpw; cs++) {
        if (cs + 1 < cpw) { load_stage((cs + 1) & 1, cs + 1); cp_wait<1>(); }
        else              { cp_wait<0>(); }
        __syncthreads();
        const int st = cs & 1;
        const float* xb = &xs[((st*8 + wid)*32)*32];
        const float* wb = &ws[((st*8 + wid)*32)*32];
#pragma unroll
        for (int kkq = 0; kkq < 8; kkq++) {
            ulonglong2 xv[4];
#pragma unroll
            for (int r = 0; r < 4; r++)
                xv[r] = *(const ulonglong2*)&xb[(rg*4 + r)*32 + ((kkq ^ rg) << 2)];
#pragma unroll
            for (int c = 0; c < 8; c++) {
                ulonglong2 wv = *(const ulonglong2*)&wb[(cg*8 + c)*32 + ((kkq ^ cg) << 2)];
#pragma unroll
                for (int r = 0; r < 4; r++) {
                    acc[r][c] = fma2(xv[r].x, wv.x, acc[r][c]);
                    acc[r][c] = fma2(xv[r].y, wv.y, acc[r][c]);
                }
            }
        }
        __syncthreads();
    }

    // deterministic 8-way k-reduction through smem (stride 33), then pointwise
    float* red = smem;   // overlay; mainloop ended with __syncthreads
#pragma unroll
    for (int r = 0; r < 4; r++)
#pragma unroll
        for (int c = 0; c < 8; c++)
            red[(wid*32 + rg*4 + r)*33 + cg*8 + c] = acc_sum(acc[r][c]);
    __syncthreads();

    {
        float g4[4];
#pragma unroll
        for (int gt = 0; gt < 4; gt++) {
            int col = gt*8 + phh;
            float v = 0.f;
#pragma unroll
            for (int w = 0; w < 8; w++) v += red[(w*32 + pb)*33 + col];
            g4[gt] = v + pv[gt];
        }
        float cp = c_st[pb*H + hmy];
        float cn = sigf(g4[1]) * cp + sigf(g4[0]) * tanhf(g4[2]);
        c_st[pb*H + hmy]  = cn;
        h_out[pb*H + hmy] = sigf(g4[3]) * tanhf(cn);
    }
    __syncthreads();   // protect overlay before next phase's loads
}

// ---------------- persistent recurrence kernel ----------------
__global__ __launch_bounds__(256, 1) void recurrence(
    const float* __restrict__ pre_pos, const float* __restrict__ pre_w0,
    const float* __restrict__ pWih,  const float* __restrict__ pWhh,
    const float* __restrict__ w0Wih, const float* __restrict__ w0Whh,
    const float* __restrict__ w1Wih, const float* __restrict__ w1Whh,
    const float* __restrict__ w1bih, const float* __restrict__ w1bhh)
{
    extern __shared__ float smem[];
    for (int t = 0; t < Tt; t++) {
        // pos cell: x = [pos_emb ; wh1_prev] (pre) + recurrent ph_prev
        cell_phase(smem, pre_pos + (size_t)t * Bb * 4 * PH, nullptr, nullptr,
                   g_wh1 + (size_t)t * Bb * WH, WH, pWih + PE, PE + WH, WH,
                   g_ph  + (size_t)t * Bb * PH, PH, pWhh,      PH,      PH,
                   g_pc, g_ph + (size_t)(t+1) * Bb * PH, PH);
        gsync();
        // word cell0: x = [word_emb ; ph_new] (pre) + recurrent wh0_prev
        cell_phase(smem, pre_w0 + (size_t)t * Bb * 4 * WH, nullptr, nullptr,
                   g_ph  + (size_t)(t+1) * Bb * PH, PH, w0Wih + WE, WE + PH, PH,
                   g_wh0 + (size_t)t * Bb * WH,     WH, w0Whh,      WH,      WH,
                   g_wc0, g_wh0 + (size_t)(t+1) * Bb * WH, WH);
        gsync();
        // word cell1: x = wh0_new + recurrent wh1_prev
        cell_phase(smem, nullptr, w1bih, w1bhh,
                   g_wh0 + (size_t)(t+1) * Bb * WH, WH, w1Wih, WH, WH,
                   g_wh1 + (size_t)t * Bb * WH,     WH, w1Whh, WH, WH,
                   g_wc1, g_wh1 + (size_t)(t+1) * Bb * WH, WH);
        gsync();
    }
}

// ---------------- pos head: Linear(256->45) + log-softmax ----------------
__global__ void pos_head(const float* __restrict__ pouts,
                         const float* __restrict__ W, const float* __restrict__ bias,
                         float* __restrict__ out)
{
    __shared__ float sv[64];
    __shared__ float sred[2];
    int r = blockIdx.x, jt = threadIdx.x;
    const float* x = pouts + (size_t)r * PH;
    float v = 0.f;
    if (jt < PV) {
        float s = bias[jt];
        const float* w = W + (size_t)jt * PH;
#pragma unroll 4
        for (int k = 0; k < PH; k++) s += x[k] * w[k];
        v = s;
    }
    sv[jt] = v;
    __syncthreads();
    if (jt == 0) {
        float m = sv[0];
        for (int i = 1; i < PV; i++) m = fmaxf(m, sv[i]);
        float sum = 0.f;
        for (int i = 0; i < PV; i++) sum += expf(sv[i] - m);
        sred[0] = m; sred[1] = logf(sum);
    }
    __syncthreads();
    if (jt < PV) out[(size_t)r * PV + jt] = v - sred[0] - sred[1];
}

// ---------------- word log-softmax in place (vectorized) ----------------
__global__ __launch_bounds__(512) void wlogsoftmax(float* __restrict__ w)
{
    __shared__ float red[512];
    int r = blockIdx.x, tid = threadIdx.x;
    float4* row = (float4*)(w + (size_t)r * WV);
    const int NV = WV / 4;
    float m = -1e30f;
    for (int i = tid; i < NV; i += 512) {
        float4 v = row[i];
        m = fmaxf(m, fmaxf(fmaxf(v.x, v.y), fmaxf(v.z, v.w)));
    }
    red[tid] = m; __syncthreads();
    for (int s = 256; s > 0; s >>= 1) { if (tid < s) red[tid] = fmaxf(red[tid], red[tid+s]); __syncthreads(); }
    m = red[0]; __syncthreads();
    float sum = 0.f;
    for (int i = tid; i < NV; i += 512) {
        float4 v = row[i];
        sum += expf(v.x - m) + expf(v.y - m) + expf(v.z - m) + expf(v.w - m);
    }
    red[tid] = sum; __syncthreads();
    for (int s = 256; s > 0; s >>= 1) { if (tid < s) red[tid] += red[tid+s]; __syncthreads(); }
    float lg = m + logf(red[0]);
    for (int i = tid; i < NV; i += 512) {
        float4 v = row[i];
        v.x -= lg; v.y -= lg; v.z -= lg; v.w -= lg;
        row[i] = v;
    }
}

// ---------------- launch ----------------
extern "C" void kernel_launch(void* const* d_in, const int* in_sizes, int n_in,
                              void* d_out, int out_size)
{
    const int*   pos      = (const int*)d_in[0];
    const int*   word     = (const int*)d_in[1];
    const float* pos_emb  = (const float*)d_in[2];
    const float* word_emb = (const float*)d_in[3];
    const float* pWih     = (const float*)d_in[4];
    const float* pWhh     = (const float*)d_in[5];
    const float* pbih     = (const float*)d_in[6];
    const float* pbhh     = (const float*)d_in[7];
    const float* w0Wih    = (const float*)d_in[8];
    const float* w0Whh    = (const float*)d_in[9];
    const float* w0bih    = (const float*)d_in[10];
    const float* w0bhh    = (const float*)d_in[11];
    const float* w1Wih    = (const float*)d_in[12];
    const float* w1Whh    = (const float*)d_in[13];
    const float* w1bih    = (const float*)d_in[14];
    const float* w1bhh    = (const float*)d_in[15];
    const float* pprojW   = (const float*)d_in[16];
    const float* pprojb   = (const float*)d_in[17];
    const float* wp1W     = (const float*)d_in[18];
    const float* wp1b     = (const float*)d_in[19];
    const float* wp2b     = (const float*)d_in[20];

    float *pA, *pA0, *ph, *wh1, *wmid;
    cudaGetSymbolAddress((void**)&pA,   g_Apos);
    cudaGetSymbolAddress((void**)&pA0,  g_Aw0);
    cudaGetSymbolAddress((void**)&ph,   g_ph);
    cudaGetSymbolAddress((void**)&wh1,  g_wh1);
    cudaGetSymbolAddress((void**)&wmid, g_wmid);

    const int smem_rec = 2 * 2 * 8 * 32 * 32 * 4;   // 131072 B
    cudaFuncSetAttribute(recurrence, cudaFuncAttributeMaxDynamicSharedMemorySize, smem_rec);

    zero_init<<<(Bb*WH + 255) / 256, 256>>>();

    // precompute input projections (+ both biases) for all (t,b) rows
    gemm_nt<<<dim3(4*PH/64, Tt*Bb/64), 256>>>(pos_emb, pos, PE, pWih, PE+WH,
                                              pA, 4*PH, PE, pbih, pbhh);
    gemm_nt<<<dim3(4*WH/64, Tt*Bb/64), 256>>>(word_emb, word, WE, w0Wih, WE+PH,
                                              pA0, 4*WH, WE, w0bih, w0bhh);

    // whole recurrence in one persistent kernel
    recurrence<<<GRID, 256, smem_rec>>>(pA, pA0, pWih, pWhh,
                                        w0Wih, w0Whh, w1Wih, w1Whh,
                                        w1bih, w1bhh);

    float* out  = (float*)d_out;
    float* wout = out + (size_t)Tt * Bb * PV;

    // w_mid = w_outs @ wp1_W^T + wp1_b
    gemm_nt<<<dim3(WE/64, Tt*Bb/64), 256>>>(wh1 + (size_t)Bb * WH, nullptr, WH,
                                            wp1W, WH, wmid, WE, WH, wp1b, nullptr);
    // word logits = w_mid @ word_emb^T + wp2_b, directly into d_out
    gemm_nt<<<dim3(WV/64, Tt*Bb/64), 256>>>(wmid, nullptr, WE,
                                            word_emb, WE, wout, WV, WE, wp2b, nullptr);
    // pos head (fused log-softmax)
    pos_head<<<Tt*Bb, 64>>>(ph + (size_t)Bb * PH, pprojW, pprojb, out);
    // word log-softmax in place
    wlogsoftmax<<<Tt*Bb, 512>>>(wout);
}